// round 14
// baseline (speedup 1.0000x reference)
#include <cuda_runtime.h>
#include <cuda_fp16.h>
#include <math.h>
#include <stdint.h>

#define N_ART 50000
#define N_ENT 100000
#define N_FACT 50000
#define NEDGE 200000
#define FEATD 769
#define HIDD 128

#define K1S 800
#define K2S 128

// ---------------------------------------------------------------------------
// Scratch
// ---------------------------------------------------------------------------
__device__ __half g_B5[44800000];               // 5 lin_l outputs (dst rows), fp16
__device__ __half g_P5[44800000];               // 5 lin_r outputs (src rows), fp16
__device__ float g_z[3200000];
__device__ __half g_Xh[160000000];              // fp16 features: 200k x 800 (art|ent|fact)
__device__ __half g_H1h[25600000];              // fp16 relu(h1): 200k x 128
__device__ __half g_W1L[512000];                // c1 lin_l fp16: 640 x 800
__device__ __half g_W1R[512000];
__device__ __half g_W2L[81920];                 // c2 lin_l fp16: 640 x 128
__device__ __half g_W2R[81920];
__device__ int g_cursor[500000];
__device__ int g_off[500160];                   // per-type CSR offsets (stride 100032)
__device__ int g_srcA[1000000];                 // per-type CSR src lists (stride 200000)

// ---------------------------------------------------------------------------
__device__ __forceinline__ uint32_t smem_u32(const void* p) {
    uint32_t a;
    asm("{ .reg .u64 t; cvta.to.shared.u64 t, %1; cvt.u32.u64 %0, t; }"
        : "=r"(a) : "l"(p));
    return a;
}

#define CP_ASYNC16(dst, src) \
    asm volatile("cp.async.cg.shared.global [%0], [%1], 16;" :: "r"(dst), "l"(src))
#define CP_COMMIT() asm volatile("cp.async.commit_group;" ::: "memory")
#define CP_WAIT1()  asm volatile("cp.async.wait_group 1;" ::: "memory")

#define SSTRB 80

struct MultiOut {
    const void* W[4];
    const float* bias[4];
    __half* C[4];
};

#define LDMX4(r0, r1, r2, r3, addr) \
    asm volatile("ldmatrix.sync.aligned.m8n8.x4.shared.b16 {%0,%1,%2,%3}, [%4];" \
                 : "=r"(r0), "=r"(r1), "=r"(r2), "=r"(r3) : "r"(addr))

#define MMA_FP16(acc, a, b) \
    asm volatile("mma.sync.aligned.m16n8k16.row.col.f32.f16.f16.f32 " \
                 "{%0,%1,%2,%3}, {%4,%5,%6,%7}, {%8,%9}, {%0,%1,%2,%3};" \
                 : "+f"((acc)[0]), "+f"((acc)[1]), "+f"((acc)[2]), "+f"((acc)[3]) \
                 : "r"((a)[0]), "r"((a)[1]), "r"((a)[2]), "r"((a)[3]), \
                   "r"((b)[0]), "r"((b)[1]))

// ---------------------------------------------------------------------------
// fp16 single-pass multi-output GEMM, 256x128 CTA tile, 64x64 warp tiles.
// C_b[M,128] = A[M,S] @ W_b[128,S]^T (+bias), fp16 out.
// grid = (NBLK, ceil(M/256)), 256 threads (8 warps, 4x2), K-chunk 32.
// SMEM: A 2x20480 | W 2x10240 = 61440 B.
// ---------------------------------------------------------------------------
#define V_OFF_A 0
#define V_OFF_W 40960
#define SMEM_V  61440

__global__ __launch_bounds__(256) void gemm_fp16_1p(
    const __half* __restrict__ A, MultiOut p, int M, int S)
{
    extern __shared__ char sm[];
    const uint32_t sb = smem_u32(sm);
    const int tid = threadIdx.x, lane = tid & 31, warp = tid >> 5;
    const int mW = (warp >> 1) * 64, nW = (warp & 1) * 64;
    const int rowBase = blockIdx.y * 256;
    const __half* __restrict__ W = (const __half*)p.W[blockIdx.x];
    const float* __restrict__ bias = p.bias[blockIdx.x];
    __half* __restrict__ C = p.C[blockIdx.x];
    const int NC = S >> 5;

    float acc[4][8][4];
#pragma unroll
    for (int i = 0; i < 4; i++)
#pragma unroll
        for (int j = 0; j < 8; j++)
#pragma unroll
            for (int q = 0; q < 4; q++) acc[i][j][q] = 0.f;

    const int lr4 = tid >> 2, lq4 = tid & 3;   // 64 rows x 4 quads (16B)

#define LOADV(c, buf) do { \
    int k0 = (c) * 32; \
    _Pragma("unroll") \
    for (int i = 0; i < 4; i++) { \
        int r = lr4 + i * 64; \
        int ga = rowBase + r; if (ga >= M) ga = M - 1; \
        CP_ASYNC16(sb + V_OFF_A + (buf) * 20480 + r * SSTRB + lq4 * 16, \
                   A + (size_t)ga * S + k0 + lq4 * 8); \
    } \
    _Pragma("unroll") \
    for (int i = 0; i < 2; i++) { \
        int r = lr4 + i * 64; \
        CP_ASYNC16(sb + V_OFF_W + (buf) * 10240 + r * SSTRB + lq4 * 16, \
                   W + (size_t)r * S + k0 + lq4 * 8); \
    } } while (0)

    LOADV(0, 0); CP_COMMIT();
    if (NC > 1) { LOADV(1, 1); }
    CP_COMMIT();

    const int a_row = lane & 15;
    const int a_sel = (lane >> 4) & 1;
    const int b_row = (lane & 7) + ((lane & 16) >> 1);
    const int b_sel = (lane >> 3) & 1;

    for (int c = 0; c < NC; c++) {
        CP_WAIT1();
        __syncthreads();
        uint32_t abase = sb + V_OFF_A + (uint32_t)(c & 1) * 20480;
        uint32_t wbase = sb + V_OFF_W + (uint32_t)(c & 1) * 10240;
#pragma unroll
        for (int kh = 0; kh < 2; kh++) {
            uint32_t ar[4][4], br[8][2];
#pragma unroll
            for (int mi = 0; mi < 4; mi++) {
                uint32_t addr = abase + (mW + mi * 16 + a_row) * SSTRB
                                + kh * 32 + a_sel * 16;
                LDMX4(ar[mi][0], ar[mi][1], ar[mi][2], ar[mi][3], addr);
            }
#pragma unroll
            for (int pi = 0; pi < 4; pi++) {
                uint32_t addr = wbase + (nW + pi * 16 + b_row) * SSTRB
                                + kh * 32 + b_sel * 16;
                LDMX4(br[2 * pi][0], br[2 * pi][1],
                      br[2 * pi + 1][0], br[2 * pi + 1][1], addr);
            }
#pragma unroll
            for (int mi = 0; mi < 4; mi++)
#pragma unroll
                for (int ni = 0; ni < 8; ni++)
                    MMA_FP16(acc[mi][ni], ar[mi], br[ni]);
        }
        __syncthreads();
        if (c + 2 < NC) LOADV(c + 2, c & 1);
        CP_COMMIT();
    }
#undef LOADV

    const int g = lane >> 2, t = lane & 3;
#pragma unroll
    for (int mi = 0; mi < 4; mi++) {
        int r0 = rowBase + mW + mi * 16 + g;
#pragma unroll
        for (int ni = 0; ni < 8; ni++) {
            int col = nW + ni * 8 + t * 2;
            float bx = 0.f, by2 = 0.f;
            if (bias) { bx = bias[col]; by2 = bias[col + 1]; }
            if (r0 < M) {
                __half2 v = __floats2half2_rn(acc[mi][ni][0] + bx, acc[mi][ni][1] + by2);
                *(__half2*)(C + (size_t)r0 * 128 + col) = v;
            }
            if (r0 + 8 < M) {
                __half2 v = __floats2half2_rn(acc[mi][ni][2] + bx, acc[mi][ni][3] + by2);
                *(__half2*)(C + (size_t)(r0 + 8) * 128 + col) = v;
            }
        }
    }
}

// ---------------------------------------------------------------------------
// Converts
// ---------------------------------------------------------------------------
__global__ void conv_feat3(const float* __restrict__ x0, const float* __restrict__ x1,
                           const float* __restrict__ x2, __half* __restrict__ outA)
{
    int row = blockIdx.x;
    int k = threadIdx.x * 4;
    if (k >= K1S) return;
    const float* src;
    if (row < N_ART) src = x0 + (size_t)row * FEATD;
    else if (row < N_ART + N_ENT) src = x1 + (size_t)(row - N_ART) * FEATD;
    else src = x2 + (size_t)(row - N_ART - N_ENT) * FEATD;
    __half h[4];
#pragma unroll
    for (int j = 0; j < 4; j++) {
        int kk = k + j;
        h[j] = __float2half((kk < FEATD) ? src[kk] : 0.f);
    }
    *(uint2*)(outA + (size_t)row * K1S + k) = *(uint2*)h;
}

__global__ void conv_fp16(const float* __restrict__ in,
                          __half* __restrict__ outA, int K, int S)
{
    int row = blockIdx.x;
    int k = threadIdx.x * 4;
    if (k >= S) return;
    const float* src = in + (size_t)row * K;
    __half h[4];
#pragma unroll
    for (int j = 0; j < 4; j++) {
        int kk = k + j;
        h[j] = __float2half((kk < K) ? src[kk] : 0.f);
    }
    *(uint2*)(outA + (size_t)row * S + k) = *(uint2*)h;
}

// ---------------------------------------------------------------------------
// CSR build
// ---------------------------------------------------------------------------
struct EdgePtrs { const int* e[5]; };

__global__ void count5_k(EdgePtrs ep, int* __restrict__ cnt, int E)
{
    int i = blockIdx.y;
    int e = blockIdx.x * blockDim.x + threadIdx.x;
    if (e < E) atomicAdd(&cnt[i * 100000 + ep.e[i][E + e]], 1);
}

__constant__ int c_dstN[5] = {100000, 50000, 50000, 50000, 100000};

__global__ void scan5_k(const int* __restrict__ cnt, int* __restrict__ off)
{
    __shared__ int sh[32];
    __shared__ int carry;
    int type = blockIdx.x;
    const int n = c_dstN[type];
    const int* c = cnt + type * 100000;
    int* o = off + type * 100032;
    int tid = threadIdx.x, lane = tid & 31, w = tid >> 5;
    if (tid == 0) carry = 0;
    __syncthreads();
    for (int base = 0; base < n; base += 1024) {
        int i = base + tid;
        int v = (i < n) ? c[i] : 0;
        int x = v;
#pragma unroll
        for (int d = 1; d < 32; d <<= 1) {
            int y = __shfl_up_sync(0xffffffffu, x, d);
            if (lane >= d) x += y;
        }
        if (lane == 31) sh[w] = x;
        __syncthreads();
        if (w == 0) {
            int s = sh[lane];
#pragma unroll
            for (int d = 1; d < 32; d <<= 1) {
                int y = __shfl_up_sync(0xffffffffu, s, d);
                if (lane >= d) s += y;
            }
            sh[lane] = s;
        }
        __syncthreads();
        int excl = x - v + (w > 0 ? sh[w - 1] : 0) + carry;
        if (i < n) o[i] = excl;
        __syncthreads();
        if (tid == 1023) carry = excl + v;
        __syncthreads();
    }
    if (tid == 0) o[n] = carry;
}

__global__ void fill5_k(EdgePtrs ep, const int* __restrict__ off, int* __restrict__ cursor,
                        int* __restrict__ srcA, int E)
{
    int i = blockIdx.y;
    int e = blockIdx.x * blockDim.x + threadIdx.x;
    if (e >= E) return;
    int d = ep.e[i][E + e];
    int pos = atomicAdd(&cursor[i * 100000 + d], 1);
    srcA[i * 200000 + off[i * 100032 + d] + pos] = ep.e[i][e];
}

// ---------------------------------------------------------------------------
// Fused gather + mean + lin_l + L2-normalize + relu + sum over <=2 edge types
// ---------------------------------------------------------------------------
__device__ __forceinline__ float4 ld_half4(const __half* p) {
    uint2 raw = *(const uint2*)p;
    __half2 h0 = *(__half2*)&raw.x;
    __half2 h1 = *(__half2*)&raw.y;
    float2 f0 = __half22float2(h0);
    float2 f1 = __half22float2(h1);
    return make_float4(f0.x, f0.y, f1.x, f1.y);
}

template<bool TWO, bool OUT_HALF>
__global__ void combine2(
    const __half* __restrict__ B0, const __half* __restrict__ P0,
    const int* __restrict__ off0, const int* __restrict__ src0,
    const __half* __restrict__ B1, const __half* __restrict__ P1,
    const int* __restrict__ off1, const int* __restrict__ src1,
    void* __restrict__ out, int n)
{
    int w = (blockIdx.x * blockDim.x + threadIdx.x) >> 5;
    int lane = threadIdx.x & 31;
    if (w >= n) return;
    size_t o = (size_t)w * HIDD + lane * 4;
    float4 r = make_float4(0.f, 0.f, 0.f, 0.f);

    {
        float4 b = ld_half4(B0 + o);
        int beg = __ldg(off0 + w), end = __ldg(off0 + w + 1);
        float4 a = make_float4(0.f, 0.f, 0.f, 0.f);
        for (int e = beg; e < end; e++) {
            int s = __ldg(src0 + e);
            float4 p = ld_half4(P0 + (size_t)s * HIDD + lane * 4);
            a.x += p.x; a.y += p.y; a.z += p.z; a.w += p.w;
        }
        float inv = 1.0f / fmaxf((float)(end - beg), 1.0f);
        float4 t;
        t.x = b.x + a.x * inv; t.y = b.y + a.y * inv;
        t.z = b.z + a.z * inv; t.w = b.w + a.w * inv;
        float ss = t.x * t.x + t.y * t.y + t.z * t.z + t.w * t.w;
#pragma unroll
        for (int sh = 16; sh; sh >>= 1) ss += __shfl_xor_sync(0xffffffffu, ss, sh);
        float sc = 1.0f / fmaxf(sqrtf(ss), 1e-12f);
        r.x += t.x * sc; r.y += t.y * sc; r.z += t.z * sc; r.w += t.w * sc;
    }
    if (TWO) {
        float4 b = ld_half4(B1 + o);
        int beg = __ldg(off1 + w), end = __ldg(off1 + w + 1);
        float4 a = make_float4(0.f, 0.f, 0.f, 0.f);
        for (int e = beg; e < end; e++) {
            int s = __ldg(src1 + e);
            float4 p = ld_half4(P1 + (size_t)s * HIDD + lane * 4);
            a.x += p.x; a.y += p.y; a.z += p.z; a.w += p.w;
        }
        float inv = 1.0f / fmaxf((float)(end - beg), 1.0f);
        float4 t;
        t.x = b.x + a.x * inv; t.y = b.y + a.y * inv;
        t.z = b.z + a.z * inv; t.w = b.w + a.w * inv;
        float ss = t.x * t.x + t.y * t.y + t.z * t.z + t.w * t.w;
#pragma unroll
        for (int sh = 16; sh; sh >>= 1) ss += __shfl_xor_sync(0xffffffffu, ss, sh);
        float sc = 1.0f / fmaxf(sqrtf(ss), 1e-12f);
        r.x += t.x * sc; r.y += t.y * sc; r.z += t.z * sc; r.w += t.w * sc;
    }
    r.x = fmaxf(r.x, 0.f); r.y = fmaxf(r.y, 0.f);
    r.z = fmaxf(r.z, 0.f); r.w = fmaxf(r.w, 0.f);

    if (OUT_HALF) {
        __half h[4];
        h[0] = __float2half(r.x); h[1] = __float2half(r.y);
        h[2] = __float2half(r.z); h[3] = __float2half(r.w);
        *(uint2*)((__half*)out + o) = *(uint2*)h;
    } else {
        *(float4*)((float*)out + o) = r;
    }
}

// ---------------------------------------------------------------------------
// SIMT GEMM for the 64-wide head
// ---------------------------------------------------------------------------
template<bool RELU_OUT>
__global__ __launch_bounds__(256) void gemm_tn(
    const float* __restrict__ A, const float* __restrict__ W,
    const float* __restrict__ bias, float* __restrict__ C,
    int M, int N, int K)
{
    __shared__ float As[8][128];
    __shared__ float Ws[8][128];
    const int tid = threadIdx.x;
    const int tx = tid & 15, ty = tid >> 4;
    const int rowBase = blockIdx.y * 128;

    float acc[8][8];
#pragma unroll
    for (int i = 0; i < 8; i++)
#pragma unroll
        for (int j = 0; j < 8; j++) acc[i][j] = 0.f;

    for (int k0 = 0; k0 < K; k0 += 8) {
#pragma unroll
        for (int t = 0; t < 4; t++) {
            int idx = tid + t * 256;
            int k = idx & 7, r = idx >> 3;
            int row = rowBase + r, kk = k0 + k;
            float v = 0.f;
            if (row < M && kk < K) v = A[(size_t)row * K + kk];
            As[k][r] = v;
        }
#pragma unroll
        for (int t = 0; t < 4; t++) {
            int idx = tid + t * 256;
            int k = idx & 7, c = idx >> 3;
            int kk = k0 + k;
            float v = 0.f;
            if (c < N && kk < K) v = W[(size_t)c * K + kk];
            Ws[k][c] = v;
        }
        __syncthreads();
#pragma unroll
        for (int k = 0; k < 8; k++) {
            float4 a0 = *(const float4*)&As[k][ty * 8];
            float4 a1 = *(const float4*)&As[k][ty * 8 + 4];
            float4 b0 = *(const float4*)&Ws[k][tx * 8];
            float4 b1 = *(const float4*)&Ws[k][tx * 8 + 4];
            float av[8] = {a0.x, a0.y, a0.z, a0.w, a1.x, a1.y, a1.z, a1.w};
            float bv[8] = {b0.x, b0.y, b0.z, b0.w, b1.x, b1.y, b1.z, b1.w};
#pragma unroll
            for (int i = 0; i < 8; i++)
#pragma unroll
                for (int j = 0; j < 8; j++) acc[i][j] += av[i] * bv[j];
        }
        __syncthreads();
    }

#pragma unroll
    for (int i = 0; i < 8; i++) {
        int row = rowBase + ty * 8 + i;
        if (row < M) {
#pragma unroll
            for (int j = 0; j < 8; j++) {
                int col = tx * 8 + j;
                if (col < N) {
                    float v = acc[i][j] + bias[col];
                    if (RELU_OUT) v = fmaxf(v, 0.f);
                    C[(size_t)row * N + col] = v;
                }
            }
        }
    }
}

__global__ void head2_k(const float* __restrict__ Z, const float* __restrict__ W2,
                        const float* __restrict__ b2, float* __restrict__ out, int n)
{
    int row = blockIdx.x * blockDim.x + threadIdx.x;
    if (row >= n) return;
    float acc0 = b2[0], acc1 = b2[1];
    const float* z = Z + (size_t)row * 64;
#pragma unroll
    for (int k = 0; k < 64; k++) {
        float zv = z[k];
        acc0 += zv * __ldg(W2 + k);
        acc1 += zv * __ldg(W2 + 64 + k);
    }
    out[row * 2 + 0] = acc0;
    out[row * 2 + 1] = acc1;
}

// ---------------------------------------------------------------------------
extern "C" void kernel_launch(void* const* d_in, const int* in_sizes, int n_in,
                              void* d_out_, int out_size)
{
    const float* x[3] = {(const float*)d_in[0], (const float*)d_in[1], (const float*)d_in[2]};
    const int nn[3] = {N_ART, N_ENT, N_FACT};
    const int* ei[5];
    for (int i = 0; i < 5; i++) ei[i] = (const int*)d_in[3 + i];
    const float* c1llw = (const float*)d_in[8];
    const float* c1llb = (const float*)d_in[9];
    const float* c1lrw = (const float*)d_in[10];
    const float* c2llw = (const float*)d_in[11];
    const float* c2llb = (const float*)d_in[12];
    const float* c2lrw = (const float*)d_in[13];
    const float* hw1 = (const float*)d_in[14];
    const float* hb1 = (const float*)d_in[15];
    const float* hw2 = (const float*)d_in[16];
    const float* hb2 = (const float*)d_in[17];
    float* out = (float*)d_out_;

    static const size_t BOFF[5] = {0, 100000, 150000, 200000, 250000};
    static const size_t POFF[5] = {0, 50000, 100000, 200000, 300000};

    float *Z;
    __half *B5, *P5, *Xh, *H1h, *W1L, *W1R, *W2L, *W2R;
    int *CUR, *OFFS, *SRCA;
    cudaGetSymbolAddress((void**)&B5, g_B5);
    cudaGetSymbolAddress((void**)&P5, g_P5);
    cudaGetSymbolAddress((void**)&Z, g_z);
    cudaGetSymbolAddress((void**)&Xh, g_Xh);
    cudaGetSymbolAddress((void**)&H1h, g_H1h);
    cudaGetSymbolAddress((void**)&W1L, g_W1L);
    cudaGetSymbolAddress((void**)&W1R, g_W1R);
    cudaGetSymbolAddress((void**)&W2L, g_W2L);
    cudaGetSymbolAddress((void**)&W2R, g_W2R);
    cudaGetSymbolAddress((void**)&CUR, g_cursor);
    cudaGetSymbolAddress((void**)&OFFS, g_off);
    cudaGetSymbolAddress((void**)&SRCA, g_srcA);

    cudaFuncSetAttribute(gemm_fp16_1p, cudaFuncAttributeMaxDynamicSharedMemorySize, SMEM_V);

    const size_t XHB[3] = {0, (size_t)N_ART * K1S, (size_t)(N_ART + N_ENT) * K1S};
    const size_t R0[3] = {0, (size_t)N_ART, (size_t)(N_ART + N_ENT)};

    __half* h1p[3] = {H1h, H1h + (size_t)N_ART * HIDD, H1h + (size_t)(N_ART + N_ENT) * HIDD};
    float* h2p[3] = {out + 100000,
                     out + 100000 + (size_t)N_ART * HIDD,
                     out + 100000 + (size_t)(N_ART + N_ENT) * HIDD};

    const int NBLK[3] = {3, 4, 3};
    const int LLe[3][2] = {{2, -1}, {0, 4}, {1, 3}};
    const int LRe[3][2] = {{0, 1}, {2, 3}, {4, -1}};

    const size_t WB1B = (size_t)128 * K1S * 2;
    const size_t WB2B = (size_t)128 * K2S * 2;

    auto make_outs = [&](int layer, int t) {
        MultiOut p;
        const char* WL = layer ? (const char*)W2L : (const char*)W1L;
        const char* WR = layer ? (const char*)W2R : (const char*)W1R;
        const float* bb = layer ? c2llb : c1llb;
        const size_t WBB = layer ? WB2B : WB1B;
        int nb = 0;
        for (int j = 0; j < 2; j++) {
            int e = LLe[t][j];
            if (e < 0) break;
            p.W[nb] = WL + (size_t)e * WBB;
            p.bias[nb] = bb + e * HIDD;
            p.C[nb] = B5 + BOFF[e] * HIDD;
            nb++;
        }
        for (int j = 0; j < 2; j++) {
            int e = LRe[t][j];
            if (e < 0) break;
            p.W[nb] = WR + (size_t)e * WBB;
            p.bias[nb] = nullptr;
            p.C[nb] = P5 + POFF[e] * HIDD;
            nb++;
        }
        return p;
    };

    // --- launches 0-2: converts needed for layer-1 GEMMs ---
    conv_feat3<<<200000, 256>>>(x[0], x[1], x[2], Xh);
    conv_fp16<<<640, 256>>>(c1llw, W1L, FEATD, K1S);
    conv_fp16<<<640, 256>>>(c1lrw, W1R, FEATD, K1S);

    // --- launches 3-5: layer-1 GEMMs (ncu capture lands here) ---
    for (int t = 1; t >= 0; t--) {
        MultiOut p = make_outs(0, t);
        gemm_fp16_1p<<<dim3(NBLK[t], (nn[t] + 255) / 256), 256, SMEM_V>>>(
            Xh + XHB[t], p, nn[t], K1S);
    }
    {
        MultiOut p = make_outs(0, 2);
        gemm_fp16_1p<<<dim3(NBLK[2], (nn[2] + 255) / 256), 256, SMEM_V>>>(
            Xh + XHB[2], p, nn[2], K1S);
    }

    // --- CSR build + W2 converts ---
    EdgePtrs ep;
    for (int i = 0; i < 5; i++) ep.e[i] = ei[i];
    cudaMemsetAsync(CUR, 0, 500000 * sizeof(int));
    count5_k<<<dim3((NEDGE + 255) / 256, 5), 256>>>(ep, CUR, NEDGE);
    scan5_k<<<5, 1024>>>(CUR, OFFS);
    cudaMemsetAsync(CUR, 0, 500000 * sizeof(int));
    fill5_k<<<dim3((NEDGE + 255) / 256, 5), 256>>>(ep, OFFS, CUR, SRCA, NEDGE);
    conv_fp16<<<640, 32>>>(c2llw, W2L, HIDD, K2S);
    conv_fp16<<<640, 32>>>(c2lrw, W2R, HIDD, K2S);

    // --- layer-1 combines: relu fused, fp16 out directly into H1h ---
    combine2<false, true><<<(N_ART + 7) / 8, 256>>>(
        B5 + BOFF[2] * HIDD, P5 + POFF[2] * HIDD, OFFS + 2 * 100032, SRCA + 2 * 200000,
        nullptr, nullptr, nullptr, nullptr, h1p[0], N_ART);
    combine2<true, true><<<(N_ENT + 7) / 8, 256>>>(
        B5 + BOFF[0] * HIDD, P5 + POFF[0] * HIDD, OFFS + 0 * 100032, SRCA + 0 * 200000,
        B5 + BOFF[4] * HIDD, P5 + POFF[4] * HIDD, OFFS + 4 * 100032, SRCA + 4 * 200000,
        h1p[1], N_ENT);
    combine2<true, true><<<(N_FACT + 7) / 8, 256>>>(
        B5 + BOFF[1] * HIDD, P5 + POFF[1] * HIDD, OFFS + 1 * 100032, SRCA + 1 * 200000,
        B5 + BOFF[3] * HIDD, P5 + POFF[3] * HIDD, OFFS + 3 * 100032, SRCA + 3 * 200000,
        h1p[2], N_FACT);

    // --- layer-2 GEMMs (fp16 single-pass) ---
    for (int t = 1; t >= 0; t--) {
        MultiOut p = make_outs(1, t);
        gemm_fp16_1p<<<dim3(NBLK[t], (nn[t] + 255) / 256), 256, SMEM_V>>>(
            H1h + R0[t] * K2S, p, nn[t], K2S);
    }
    {
        MultiOut p = make_outs(1, 2);
        gemm_fp16_1p<<<dim3(NBLK[2], (nn[2] + 255) / 256), 256, SMEM_V>>>(
            H1h + R0[2] * K2S, p, nn[2], K2S);
    }

    // --- layer-2 combines: relu fused, fp32 out (d_out dtype) ---
    combine2<false, false><<<(N_ART + 7) / 8, 256>>>(
        B5 + BOFF[2] * HIDD, P5 + POFF[2] * HIDD, OFFS + 2 * 100032, SRCA + 2 * 200000,
        nullptr, nullptr, nullptr, nullptr, h2p[0], N_ART);
    combine2<true, false><<<(N_ENT + 7) / 8, 256>>>(
        B5 + BOFF[0] * HIDD, P5 + POFF[0] * HIDD, OFFS + 0 * 100032, SRCA + 0 * 200000,
        B5 + BOFF[4] * HIDD, P5 + POFF[4] * HIDD, OFFS + 4 * 100032, SRCA + 4 * 200000,
        h2p[1], N_ENT);
    combine2<true, false><<<(N_FACT + 7) / 8, 256>>>(
        B5 + BOFF[1] * HIDD, P5 + POFF[1] * HIDD, OFFS + 1 * 100032, SRCA + 1 * 200000,
        B5 + BOFF[3] * HIDD, P5 + POFF[3] * HIDD, OFFS + 3 * 100032, SRCA + 3 * 200000,
        h2p[2], N_FACT);

    // --- head MLP ---
    gemm_tn<true><<<dim3(1, (N_ART + 127) / 128), 256>>>(
        out + 100000, hw1, hb1, Z, N_ART, 64, HIDD);
    head2_k<<<(N_ART + 255) / 256, 256>>>(Z, hw2, hb2, out, N_ART);
}

// round 15
// speedup vs baseline: 1.1330x; 1.1330x over previous
#include <cuda_runtime.h>
#include <cuda_fp16.h>
#include <math.h>
#include <stdint.h>

#define N_ART 50000
#define N_ENT 100000
#define N_FACT 50000
#define NEDGE 200000
#define FEATD 769
#define HIDD 128

#define K1S 800
#define K2S 128

// ---------------------------------------------------------------------------
// Scratch
// ---------------------------------------------------------------------------
__device__ __half g_B5[44800000];               // 5 lin_l outputs (dst rows), fp16
__device__ __half g_P5[44800000];               // 5 lin_r outputs (src rows), fp16
__device__ float g_z[3200000];
__device__ __half g_Xh[160000000];              // fp16 features: 200k x 800 (art|ent|fact)
__device__ __half g_H1h[25600000];              // fp16 relu(h1): 200k x 128
__device__ __half g_W1L[512000];                // c1 lin_l fp16: 640 x 800
__device__ __half g_W1R[512000];
__device__ __half g_W2L[81920];                 // c2 lin_l fp16: 640 x 128
__device__ __half g_W2R[81920];
__device__ int g_cursor[500000];
__device__ int g_off[500160];                   // per-type CSR offsets (stride 100032)
__device__ int g_srcA[1000000];                 // per-type CSR src lists (stride 200000)

// ---------------------------------------------------------------------------
__device__ __forceinline__ uint32_t smem_u32(const void* p) {
    uint32_t a;
    asm("{ .reg .u64 t; cvta.to.shared.u64 t, %1; cvt.u32.u64 %0, t; }"
        : "=r"(a) : "l"(p));
    return a;
}

#define CP_ASYNC16(dst, src) \
    asm volatile("cp.async.cg.shared.global [%0], [%1], 16;" :: "r"(dst), "l"(src))
#define CP_COMMIT() asm volatile("cp.async.commit_group;" ::: "memory")
#define CP_WAIT1()  asm volatile("cp.async.wait_group 1;" ::: "memory")

#define SSTRB 80

struct MultiOut {
    const void* W[4];
    const float* bias[4];
    __half* C[4];
};

#define LDMX4(r0, r1, r2, r3, addr) \
    asm volatile("ldmatrix.sync.aligned.m8n8.x4.shared.b16 {%0,%1,%2,%3}, [%4];" \
                 : "=r"(r0), "=r"(r1), "=r"(r2), "=r"(r3) : "r"(addr))

#define MMA_FP16(acc, a, b) \
    asm volatile("mma.sync.aligned.m16n8k16.row.col.f32.f16.f16.f32 " \
                 "{%0,%1,%2,%3}, {%4,%5,%6,%7}, {%8,%9}, {%0,%1,%2,%3};" \
                 : "+f"((acc)[0]), "+f"((acc)[1]), "+f"((acc)[2]), "+f"((acc)[3]) \
                 : "r"((a)[0]), "r"((a)[1]), "r"((a)[2]), "r"((a)[3]), \
                   "r"((b)[0]), "r"((b)[1]))

// ---------------------------------------------------------------------------
// fp16 single-pass multi-output GEMM, 128x128 CTA tile, 32x64 warp tiles,
// 3-stage cp.async pipeline, ONE __syncthreads per K-chunk.
// C_b[M,128] = A[M,S] @ W_b[128,S]^T (+bias), fp16 out.
// grid = (NBLK, ceil(M/128)), 256 threads (8 warps, 4x2), K-chunk 32.
// SMEM: 3 stages x (A 10240 + W 10240) = 61440 B -> 2 CTAs/SM.
// ---------------------------------------------------------------------------
#define ST_A(s) ((s) * 10240)
#define ST_W(s) (30720 + (s) * 10240)
#define SMEM_V  61440

__global__ __launch_bounds__(256, 2) void gemm_fp16_1p(
    const __half* __restrict__ A, MultiOut p, int M, int S)
{
    extern __shared__ char sm[];
    const uint32_t sb = smem_u32(sm);
    const int tid = threadIdx.x, lane = tid & 31, warp = tid >> 5;
    const int mQ = warp >> 1, nH = warp & 1;   // 4x2 warp grid over 128x128
    const int rowBase = blockIdx.y * 128;
    const __half* __restrict__ W = (const __half*)p.W[blockIdx.x];
    const float* __restrict__ bias = p.bias[blockIdx.x];
    __half* __restrict__ C = p.C[blockIdx.x];
    const int NC = S >> 5;

    float acc[2][8][4];
#pragma unroll
    for (int i = 0; i < 2; i++)
#pragma unroll
        for (int j = 0; j < 8; j++)
#pragma unroll
            for (int q = 0; q < 4; q++) acc[i][j][q] = 0.f;

    const int lr4 = tid >> 2, lq4 = tid & 3;   // 64 rows x 4 quads (16B)

#define LOADV(c, st) do { \
    int k0 = (c) * 32; \
    _Pragma("unroll") \
    for (int i = 0; i < 2; i++) { \
        int r = lr4 + i * 64; \
        int ga = rowBase + r; if (ga >= M) ga = M - 1; \
        CP_ASYNC16(sb + ST_A(st) + r * SSTRB + lq4 * 16, \
                   A + (size_t)ga * S + k0 + lq4 * 8); \
        CP_ASYNC16(sb + ST_W(st) + r * SSTRB + lq4 * 16, \
                   W + (size_t)r * S + k0 + lq4 * 8); \
    } } while (0)

    LOADV(0, 0); CP_COMMIT();
    if (NC > 1) { LOADV(1, 1); }
    CP_COMMIT();

    const int a_row = lane & 15;
    const int a_sel = (lane >> 4) & 1;
    const int b_row = (lane & 7) + ((lane & 16) >> 1);
    const int b_sel = (lane >> 3) & 1;

    int stage = 0;
    for (int c = 0; c < NC; c++) {
        CP_WAIT1();
        __syncthreads();
        uint32_t abase = sb + ST_A(stage);
        uint32_t wbase = sb + ST_W(stage);
#pragma unroll
        for (int kh = 0; kh < 2; kh++) {
            uint32_t ar[2][4], br[8][2];
#pragma unroll
            for (int mi = 0; mi < 2; mi++) {
                uint32_t addr = abase + (mQ * 32 + mi * 16 + a_row) * SSTRB
                                + kh * 32 + a_sel * 16;
                LDMX4(ar[mi][0], ar[mi][1], ar[mi][2], ar[mi][3], addr);
            }
#pragma unroll
            for (int pi = 0; pi < 4; pi++) {
                uint32_t addr = wbase + (nH * 64 + pi * 16 + b_row) * SSTRB
                                + kh * 32 + b_sel * 16;
                LDMX4(br[2 * pi][0], br[2 * pi][1],
                      br[2 * pi + 1][0], br[2 * pi + 1][1], addr);
            }
#pragma unroll
            for (int mi = 0; mi < 2; mi++)
#pragma unroll
                for (int ni = 0; ni < 8; ni++)
                    MMA_FP16(acc[mi][ni], ar[mi], br[ni]);
        }
        // load chunk c+2 into stage (c+2)%3 == (c-1)%3: protected by the
        // barrier above (all warps have finished reading it at iter c-1).
        if (c + 2 < NC) {
            int st2 = stage + 2; if (st2 >= 3) st2 -= 3;
            LOADV(c + 2, st2);
        }
        CP_COMMIT();
        stage = (stage + 1 == 3) ? 0 : stage + 1;
    }
#undef LOADV

    const int g = lane >> 2, t = lane & 3;
#pragma unroll
    for (int mi = 0; mi < 2; mi++) {
        int r0 = rowBase + mQ * 32 + mi * 16 + g;
#pragma unroll
        for (int ni = 0; ni < 8; ni++) {
            int col = nH * 64 + ni * 8 + t * 2;
            float bx = 0.f, by2 = 0.f;
            if (bias) { bx = bias[col]; by2 = bias[col + 1]; }
            if (r0 < M) {
                __half2 v = __floats2half2_rn(acc[mi][ni][0] + bx, acc[mi][ni][1] + by2);
                *(__half2*)(C + (size_t)r0 * 128 + col) = v;
            }
            if (r0 + 8 < M) {
                __half2 v = __floats2half2_rn(acc[mi][ni][2] + bx, acc[mi][ni][3] + by2);
                *(__half2*)(C + (size_t)(r0 + 8) * 128 + col) = v;
            }
        }
    }
}

// ---------------------------------------------------------------------------
// Converts
// ---------------------------------------------------------------------------
__global__ void conv_feat3(const float* __restrict__ x0, const float* __restrict__ x1,
                           const float* __restrict__ x2, __half* __restrict__ outA)
{
    int row = blockIdx.x;
    int k = threadIdx.x * 4;
    if (k >= K1S) return;
    const float* src;
    if (row < N_ART) src = x0 + (size_t)row * FEATD;
    else if (row < N_ART + N_ENT) src = x1 + (size_t)(row - N_ART) * FEATD;
    else src = x2 + (size_t)(row - N_ART - N_ENT) * FEATD;
    __half h[4];
#pragma unroll
    for (int j = 0; j < 4; j++) {
        int kk = k + j;
        h[j] = __float2half((kk < FEATD) ? src[kk] : 0.f);
    }
    *(uint2*)(outA + (size_t)row * K1S + k) = *(uint2*)h;
}

__global__ void conv_fp16(const float* __restrict__ in,
                          __half* __restrict__ outA, int K, int S)
{
    int row = blockIdx.x;
    int k = threadIdx.x * 4;
    if (k >= S) return;
    const float* src = in + (size_t)row * K;
    __half h[4];
#pragma unroll
    for (int j = 0; j < 4; j++) {
        int kk = k + j;
        h[j] = __float2half((kk < K) ? src[kk] : 0.f);
    }
    *(uint2*)(outA + (size_t)row * S + k) = *(uint2*)h;
}

// ---------------------------------------------------------------------------
// CSR build
// ---------------------------------------------------------------------------
struct EdgePtrs { const int* e[5]; };

__global__ void count5_k(EdgePtrs ep, int* __restrict__ cnt, int E)
{
    int i = blockIdx.y;
    int e = blockIdx.x * blockDim.x + threadIdx.x;
    if (e < E) atomicAdd(&cnt[i * 100000 + ep.e[i][E + e]], 1);
}

__constant__ int c_dstN[5] = {100000, 50000, 50000, 50000, 100000};

__global__ void scan5_k(const int* __restrict__ cnt, int* __restrict__ off)
{
    __shared__ int sh[32];
    __shared__ int carry;
    int type = blockIdx.x;
    const int n = c_dstN[type];
    const int* c = cnt + type * 100000;
    int* o = off + type * 100032;
    int tid = threadIdx.x, lane = tid & 31, w = tid >> 5;
    if (tid == 0) carry = 0;
    __syncthreads();
    for (int base = 0; base < n; base += 1024) {
        int i = base + tid;
        int v = (i < n) ? c[i] : 0;
        int x = v;
#pragma unroll
        for (int d = 1; d < 32; d <<= 1) {
            int y = __shfl_up_sync(0xffffffffu, x, d);
            if (lane >= d) x += y;
        }
        if (lane == 31) sh[w] = x;
        __syncthreads();
        if (w == 0) {
            int s = sh[lane];
#pragma unroll
            for (int d = 1; d < 32; d <<= 1) {
                int y = __shfl_up_sync(0xffffffffu, s, d);
                if (lane >= d) s += y;
            }
            sh[lane] = s;
        }
        __syncthreads();
        int excl = x - v + (w > 0 ? sh[w - 1] : 0) + carry;
        if (i < n) o[i] = excl;
        __syncthreads();
        if (tid == 1023) carry = excl + v;
        __syncthreads();
    }
    if (tid == 0) o[n] = carry;
}

__global__ void fill5_k(EdgePtrs ep, const int* __restrict__ off, int* __restrict__ cursor,
                        int* __restrict__ srcA, int E)
{
    int i = blockIdx.y;
    int e = blockIdx.x * blockDim.x + threadIdx.x;
    if (e >= E) return;
    int d = ep.e[i][E + e];
    int pos = atomicAdd(&cursor[i * 100000 + d], 1);
    srcA[i * 200000 + off[i * 100032 + d] + pos] = ep.e[i][e];
}

// ---------------------------------------------------------------------------
// Fused gather + mean + lin_l + L2-normalize + relu + sum over <=2 edge types
// ---------------------------------------------------------------------------
__device__ __forceinline__ float4 ld_half4(const __half* p) {
    uint2 raw = *(const uint2*)p;
    __half2 h0 = *(__half2*)&raw.x;
    __half2 h1 = *(__half2*)&raw.y;
    float2 f0 = __half22float2(h0);
    float2 f1 = __half22float2(h1);
    return make_float4(f0.x, f0.y, f1.x, f1.y);
}

template<bool TWO, bool OUT_HALF>
__global__ void combine2(
    const __half* __restrict__ B0, const __half* __restrict__ P0,
    const int* __restrict__ off0, const int* __restrict__ src0,
    const __half* __restrict__ B1, const __half* __restrict__ P1,
    const int* __restrict__ off1, const int* __restrict__ src1,
    void* __restrict__ out, int n)
{
    int w = (blockIdx.x * blockDim.x + threadIdx.x) >> 5;
    int lane = threadIdx.x & 31;
    if (w >= n) return;
    size_t o = (size_t)w * HIDD + lane * 4;
    float4 r = make_float4(0.f, 0.f, 0.f, 0.f);

    {
        float4 b = ld_half4(B0 + o);
        int beg = __ldg(off0 + w), end = __ldg(off0 + w + 1);
        float4 a = make_float4(0.f, 0.f, 0.f, 0.f);
        for (int e = beg; e < end; e++) {
            int s = __ldg(src0 + e);
            float4 p = ld_half4(P0 + (size_t)s * HIDD + lane * 4);
            a.x += p.x; a.y += p.y; a.z += p.z; a.w += p.w;
        }
        float inv = 1.0f / fmaxf((float)(end - beg), 1.0f);
        float4 t;
        t.x = b.x + a.x * inv; t.y = b.y + a.y * inv;
        t.z = b.z + a.z * inv; t.w = b.w + a.w * inv;
        float ss = t.x * t.x + t.y * t.y + t.z * t.z + t.w * t.w;
#pragma unroll
        for (int sh = 16; sh; sh >>= 1) ss += __shfl_xor_sync(0xffffffffu, ss, sh);
        float sc = 1.0f / fmaxf(sqrtf(ss), 1e-12f);
        r.x += t.x * sc; r.y += t.y * sc; r.z += t.z * sc; r.w += t.w * sc;
    }
    if (TWO) {
        float4 b = ld_half4(B1 + o);
        int beg = __ldg(off1 + w), end = __ldg(off1 + w + 1);
        float4 a = make_float4(0.f, 0.f, 0.f, 0.f);
        for (int e = beg; e < end; e++) {
            int s = __ldg(src1 + e);
            float4 p = ld_half4(P1 + (size_t)s * HIDD + lane * 4);
            a.x += p.x; a.y += p.y; a.z += p.z; a.w += p.w;
        }
        float inv = 1.0f / fmaxf((float)(end - beg), 1.0f);
        float4 t;
        t.x = b.x + a.x * inv; t.y = b.y + a.y * inv;
        t.z = b.z + a.z * inv; t.w = b.w + a.w * inv;
        float ss = t.x * t.x + t.y * t.y + t.z * t.z + t.w * t.w;
#pragma unroll
        for (int sh = 16; sh; sh >>= 1) ss += __shfl_xor_sync(0xffffffffu, ss, sh);
        float sc = 1.0f / fmaxf(sqrtf(ss), 1e-12f);
        r.x += t.x * sc; r.y += t.y * sc; r.z += t.z * sc; r.w += t.w * sc;
    }
    r.x = fmaxf(r.x, 0.f); r.y = fmaxf(r.y, 0.f);
    r.z = fmaxf(r.z, 0.f); r.w = fmaxf(r.w, 0.f);

    if (OUT_HALF) {
        __half h[4];
        h[0] = __float2half(r.x); h[1] = __float2half(r.y);
        h[2] = __float2half(r.z); h[3] = __float2half(r.w);
        *(uint2*)((__half*)out + o) = *(uint2*)h;
    } else {
        *(float4*)((float*)out + o) = r;
    }
}

// ---------------------------------------------------------------------------
// SIMT GEMM for the 64-wide head
// ---------------------------------------------------------------------------
template<bool RELU_OUT>
__global__ __launch_bounds__(256) void gemm_tn(
    const float* __restrict__ A, const float* __restrict__ W,
    const float* __restrict__ bias, float* __restrict__ C,
    int M, int N, int K)
{
    __shared__ float As[8][128];
    __shared__ float Ws[8][128];
    const int tid = threadIdx.x;
    const int tx = tid & 15, ty = tid >> 4;
    const int rowBase = blockIdx.y * 128;

    float acc[8][8];
#pragma unroll
    for (int i = 0; i < 8; i++)
#pragma unroll
        for (int j = 0; j < 8; j++) acc[i][j] = 0.f;

    for (int k0 = 0; k0 < K; k0 += 8) {
#pragma unroll
        for (int t = 0; t < 4; t++) {
            int idx = tid + t * 256;
            int k = idx & 7, r = idx >> 3;
            int row = rowBase + r, kk = k0 + k;
            float v = 0.f;
            if (row < M && kk < K) v = A[(size_t)row * K + kk];
            As[k][r] = v;
        }
#pragma unroll
        for (int t = 0; t < 4; t++) {
            int idx = tid + t * 256;
            int k = idx & 7, c = idx >> 3;
            int kk = k0 + k;
            float v = 0.f;
            if (c < N && kk < K) v = W[(size_t)c * K + kk];
            Ws[k][c] = v;
        }
        __syncthreads();
#pragma unroll
        for (int k = 0; k < 8; k++) {
            float4 a0 = *(const float4*)&As[k][ty * 8];
            float4 a1 = *(const float4*)&As[k][ty * 8 + 4];
            float4 b0 = *(const float4*)&Ws[k][tx * 8];
            float4 b1 = *(const float4*)&Ws[k][tx * 8 + 4];
            float av[8] = {a0.x, a0.y, a0.z, a0.w, a1.x, a1.y, a1.z, a1.w};
            float bv[8] = {b0.x, b0.y, b0.z, b0.w, b1.x, b1.y, b1.z, b1.w};
#pragma unroll
            for (int i = 0; i < 8; i++)
#pragma unroll
                for (int j = 0; j < 8; j++) acc[i][j] += av[i] * bv[j];
        }
        __syncthreads();
    }

#pragma unroll
    for (int i = 0; i < 8; i++) {
        int row = rowBase + ty * 8 + i;
        if (row < M) {
#pragma unroll
            for (int j = 0; j < 8; j++) {
                int col = tx * 8 + j;
                if (col < N) {
                    float v = acc[i][j] + bias[col];
                    if (RELU_OUT) v = fmaxf(v, 0.f);
                    C[(size_t)row * N + col] = v;
                }
            }
        }
    }
}

__global__ void head2_k(const float* __restrict__ Z, const float* __restrict__ W2,
                        const float* __restrict__ b2, float* __restrict__ out, int n)
{
    int row = blockIdx.x * blockDim.x + threadIdx.x;
    if (row >= n) return;
    float acc0 = b2[0], acc1 = b2[1];
    const float* z = Z + (size_t)row * 64;
#pragma unroll
    for (int k = 0; k < 64; k++) {
        float zv = z[k];
        acc0 += zv * __ldg(W2 + k);
        acc1 += zv * __ldg(W2 + 64 + k);
    }
    out[row * 2 + 0] = acc0;
    out[row * 2 + 1] = acc1;
}

// ---------------------------------------------------------------------------
extern "C" void kernel_launch(void* const* d_in, const int* in_sizes, int n_in,
                              void* d_out_, int out_size)
{
    const float* x[3] = {(const float*)d_in[0], (const float*)d_in[1], (const float*)d_in[2]};
    const int nn[3] = {N_ART, N_ENT, N_FACT};
    const int* ei[5];
    for (int i = 0; i < 5; i++) ei[i] = (const int*)d_in[3 + i];
    const float* c1llw = (const float*)d_in[8];
    const float* c1llb = (const float*)d_in[9];
    const float* c1lrw = (const float*)d_in[10];
    const float* c2llw = (const float*)d_in[11];
    const float* c2llb = (const float*)d_in[12];
    const float* c2lrw = (const float*)d_in[13];
    const float* hw1 = (const float*)d_in[14];
    const float* hb1 = (const float*)d_in[15];
    const float* hw2 = (const float*)d_in[16];
    const float* hb2 = (const float*)d_in[17];
    float* out = (float*)d_out_;

    static const size_t BOFF[5] = {0, 100000, 150000, 200000, 250000};
    static const size_t POFF[5] = {0, 50000, 100000, 200000, 300000};

    float *Z;
    __half *B5, *P5, *Xh, *H1h, *W1L, *W1R, *W2L, *W2R;
    int *CUR, *OFFS, *SRCA;
    cudaGetSymbolAddress((void**)&B5, g_B5);
    cudaGetSymbolAddress((void**)&P5, g_P5);
    cudaGetSymbolAddress((void**)&Z, g_z);
    cudaGetSymbolAddress((void**)&Xh, g_Xh);
    cudaGetSymbolAddress((void**)&H1h, g_H1h);
    cudaGetSymbolAddress((void**)&W1L, g_W1L);
    cudaGetSymbolAddress((void**)&W1R, g_W1R);
    cudaGetSymbolAddress((void**)&W2L, g_W2L);
    cudaGetSymbolAddress((void**)&W2R, g_W2R);
    cudaGetSymbolAddress((void**)&CUR, g_cursor);
    cudaGetSymbolAddress((void**)&OFFS, g_off);
    cudaGetSymbolAddress((void**)&SRCA, g_srcA);

    cudaFuncSetAttribute(gemm_fp16_1p, cudaFuncAttributeMaxDynamicSharedMemorySize, SMEM_V);

    const size_t XHB[3] = {0, (size_t)N_ART * K1S, (size_t)(N_ART + N_ENT) * K1S};
    const size_t R0[3] = {0, (size_t)N_ART, (size_t)(N_ART + N_ENT)};

    __half* h1p[3] = {H1h, H1h + (size_t)N_ART * HIDD, H1h + (size_t)(N_ART + N_ENT) * HIDD};
    float* h2p[3] = {out + 100000,
                     out + 100000 + (size_t)N_ART * HIDD,
                     out + 100000 + (size_t)(N_ART + N_ENT) * HIDD};

    const int NBLK[3] = {3, 4, 3};
    const int LLe[3][2] = {{2, -1}, {0, 4}, {1, 3}};
    const int LRe[3][2] = {{0, 1}, {2, 3}, {4, -1}};

    const size_t WB1B = (size_t)128 * K1S * 2;
    const size_t WB2B = (size_t)128 * K2S * 2;

    auto make_outs = [&](int layer, int t) {
        MultiOut p;
        const char* WL = layer ? (const char*)W2L : (const char*)W1L;
        const char* WR = layer ? (const char*)W2R : (const char*)W1R;
        const float* bb = layer ? c2llb : c1llb;
        const size_t WBB = layer ? WB2B : WB1B;
        int nb = 0;
        for (int j = 0; j < 2; j++) {
            int e = LLe[t][j];
            if (e < 0) break;
            p.W[nb] = WL + (size_t)e * WBB;
            p.bias[nb] = bb + e * HIDD;
            p.C[nb] = B5 + BOFF[e] * HIDD;
            nb++;
        }
        for (int j = 0; j < 2; j++) {
            int e = LRe[t][j];
            if (e < 0) break;
            p.W[nb] = WR + (size_t)e * WBB;
            p.bias[nb] = nullptr;
            p.C[nb] = P5 + POFF[e] * HIDD;
            nb++;
        }
        return p;
    };

    // --- launches 0-2: converts needed for layer-1 GEMMs ---
    conv_feat3<<<200000, 256>>>(x[0], x[1], x[2], Xh);
    conv_fp16<<<640, 256>>>(c1llw, W1L, FEATD, K1S);
    conv_fp16<<<640, 256>>>(c1lrw, W1R, FEATD, K1S);

    // --- launches 3-5: layer-1 GEMMs (ncu capture lands here) ---
    for (int t = 1; t >= 0; t--) {
        MultiOut p = make_outs(0, t);
        gemm_fp16_1p<<<dim3(NBLK[t], (nn[t] + 127) / 128), 256, SMEM_V>>>(
            Xh + XHB[t], p, nn[t], K1S);
    }
    {
        MultiOut p = make_outs(0, 2);
        gemm_fp16_1p<<<dim3(NBLK[2], (nn[2] + 127) / 128), 256, SMEM_V>>>(
            Xh + XHB[2], p, nn[2], K1S);
    }

    // --- CSR build + W2 converts ---
    EdgePtrs ep;
    for (int i = 0; i < 5; i++) ep.e[i] = ei[i];
    cudaMemsetAsync(CUR, 0, 500000 * sizeof(int));
    count5_k<<<dim3((NEDGE + 255) / 256, 5), 256>>>(ep, CUR, NEDGE);
    scan5_k<<<5, 1024>>>(CUR, OFFS);
    cudaMemsetAsync(CUR, 0, 500000 * sizeof(int));
    fill5_k<<<dim3((NEDGE + 255) / 256, 5), 256>>>(ep, OFFS, CUR, SRCA, NEDGE);
    conv_fp16<<<640, 32>>>(c2llw, W2L, HIDD, K2S);
    conv_fp16<<<640, 32>>>(c2lrw, W2R, HIDD, K2S);

    // --- layer-1 combines: relu fused, fp16 out directly into H1h ---
    combine2<false, true><<<(N_ART + 7) / 8, 256>>>(
        B5 + BOFF[2] * HIDD, P5 + POFF[2] * HIDD, OFFS + 2 * 100032, SRCA + 2 * 200000,
        nullptr, nullptr, nullptr, nullptr, h1p[0], N_ART);
    combine2<true, true><<<(N_ENT + 7) / 8, 256>>>(
        B5 + BOFF[0] * HIDD, P5 + POFF[0] * HIDD, OFFS + 0 * 100032, SRCA + 0 * 200000,
        B5 + BOFF[4] * HIDD, P5 + POFF[4] * HIDD, OFFS + 4 * 100032, SRCA + 4 * 200000,
        h1p[1], N_ENT);
    combine2<true, true><<<(N_FACT + 7) / 8, 256>>>(
        B5 + BOFF[1] * HIDD, P5 + POFF[1] * HIDD, OFFS + 1 * 100032, SRCA + 1 * 200000,
        B5 + BOFF[3] * HIDD, P5 + POFF[3] * HIDD, OFFS + 3 * 100032, SRCA + 3 * 200000,
        h1p[2], N_FACT);

    // --- layer-2 GEMMs (fp16 single-pass) ---
    for (int t = 1; t >= 0; t--) {
        MultiOut p = make_outs(1, t);
        gemm_fp16_1p<<<dim3(NBLK[t], (nn[t] + 127) / 128), 256, SMEM_V>>>(
            H1h + R0[t] * K2S, p, nn[t], K2S);
    }
    {
        MultiOut p = make_outs(1, 2);
        gemm_fp16_1p<<<dim3(NBLK[2], (nn[2] + 127) / 128), 256, SMEM_V>>>(
            H1h + R0[2] * K2S, p, nn[2], K2S);
    }

    // --- layer-2 combines: relu fused, fp32 out (d_out dtype) ---
    combine2<false, false><<<(N_ART + 7) / 8, 256>>>(
        B5 + BOFF[2] * HIDD, P5 + POFF[2] * HIDD, OFFS + 2 * 100032, SRCA + 2 * 200000,
        nullptr, nullptr, nullptr, nullptr, h2p[0], N_ART);
    combine2<true, false><<<(N_ENT + 7) / 8, 256>>>(
        B5 + BOFF[0] * HIDD, P5 + POFF[0] * HIDD, OFFS + 0 * 100032, SRCA + 0 * 200000,
        B5 + BOFF[4] * HIDD, P5 + POFF[4] * HIDD, OFFS + 4 * 100032, SRCA + 4 * 200000,
        h2p[1], N_ENT);
    combine2<true, false><<<(N_FACT + 7) / 8, 256>>>(
        B5 + BOFF[1] * HIDD, P5 + POFF[1] * HIDD, OFFS + 1 * 100032, SRCA + 1 * 200000,
        B5 + BOFF[3] * HIDD, P5 + POFF[3] * HIDD, OFFS + 3 * 100032, SRCA + 3 * 200000,
        h2p[2], N_FACT);

    // --- head MLP ---
    gemm_tn<true><<<dim3(1, (N_ART + 127) / 128), 256>>>(
        out + 100000, hw1, hb1, Z, N_ART, 64, HIDD);
    head2_k<<<(N_ART + 255) / 256, 256>>>(Z, hw2, hb2, out, N_ART);
}

// round 16
// speedup vs baseline: 1.1336x; 1.0005x over previous
#include <cuda_runtime.h>
#include <cuda_fp16.h>
#include <math.h>
#include <stdint.h>

#define N_ART 50000
#define N_ENT 100000
#define N_FACT 50000
#define NEDGE 200000
#define FEATD 769
#define HIDD 128

#define K1S 800
#define K2S 128

// ---------------------------------------------------------------------------
// Scratch
// ---------------------------------------------------------------------------
__device__ __half g_B5[44800000];               // 5 lin_l outputs (dst rows), fp16
__device__ __half g_P5[44800000];               // 5 lin_r outputs (src rows), fp16
__device__ float g_z[3200000];
__device__ __half g_Xh[160000000];              // fp16 features: 200k x 800 (art|ent|fact)
__device__ __half g_H1h[25600000];              // fp16 relu(h1): 200k x 128
__device__ __half g_W1L[512000];                // c1 lin_l fp16: 640 x 800
__device__ __half g_W1R[512000];
__device__ __half g_W2L[81920];                 // c2 lin_l fp16: 640 x 128
__device__ __half g_W2R[81920];
__device__ int g_cursor[500000];
__device__ int g_off[500160];                   // per-type CSR offsets (stride 100032)
__device__ int g_srcA[1000000];                 // per-type CSR src lists (stride 200000)

// ---------------------------------------------------------------------------
__device__ __forceinline__ uint32_t smem_u32(const void* p) {
    uint32_t a;
    asm("{ .reg .u64 t; cvta.to.shared.u64 t, %1; cvt.u32.u64 %0, t; }"
        : "=r"(a) : "l"(p));
    return a;
}

#define CP_ASYNC16(dst, src) \
    asm volatile("cp.async.cg.shared.global [%0], [%1], 16;" :: "r"(dst), "l"(src))
#define CP_COMMIT() asm volatile("cp.async.commit_group;" ::: "memory")
#define CP_WAIT1()  asm volatile("cp.async.wait_group 1;" ::: "memory")

#define SSTRB 80

struct MultiOut {
    const void* W[4];
    const float* bias[4];
    __half* C[4];
};

#define LDMX4(r0, r1, r2, r3, addr) \
    asm volatile("ldmatrix.sync.aligned.m8n8.x4.shared.b16 {%0,%1,%2,%3}, [%4];" \
                 : "=r"(r0), "=r"(r1), "=r"(r2), "=r"(r3) : "r"(addr))

#define MMA_FP16(acc, a, b) \
    asm volatile("mma.sync.aligned.m16n8k16.row.col.f32.f16.f16.f32 " \
                 "{%0,%1,%2,%3}, {%4,%5,%6,%7}, {%8,%9}, {%0,%1,%2,%3};" \
                 : "+f"((acc)[0]), "+f"((acc)[1]), "+f"((acc)[2]), "+f"((acc)[3]) \
                 : "r"((a)[0]), "r"((a)[1]), "r"((a)[2]), "r"((a)[3]), \
                   "r"((b)[0]), "r"((b)[1]))

// ---------------------------------------------------------------------------
// fp16 single-pass multi-output GEMM, 128x128 CTA tile, 32x64 warp tiles,
// 3-stage cp.async pipeline, ONE __syncthreads per K-chunk.
// C_b[M,128] = A[M,S] @ W_b[128,S]^T (+bias), fp16 out.
// grid = (NBLK, ceil(M/128)), 256 threads (8 warps, 4x2), K-chunk 32.
// SMEM: 3 stages x (A 10240 + W 10240) = 61440 B -> 2 CTAs/SM.
// ---------------------------------------------------------------------------
#define ST_A(s) ((s) * 10240)
#define ST_W(s) (30720 + (s) * 10240)
#define SMEM_V  61440

__global__ __launch_bounds__(256, 2) void gemm_fp16_1p(
    const __half* __restrict__ A, MultiOut p, int M, int S)
{
    extern __shared__ char sm[];
    const uint32_t sb = smem_u32(sm);
    const int tid = threadIdx.x, lane = tid & 31, warp = tid >> 5;
    const int mQ = warp >> 1, nH = warp & 1;   // 4x2 warp grid over 128x128
    const int rowBase = blockIdx.y * 128;
    const __half* __restrict__ W = (const __half*)p.W[blockIdx.x];
    const float* __restrict__ bias = p.bias[blockIdx.x];
    __half* __restrict__ C = p.C[blockIdx.x];
    const int NC = S >> 5;

    float acc[2][8][4];
#pragma unroll
    for (int i = 0; i < 2; i++)
#pragma unroll
        for (int j = 0; j < 8; j++)
#pragma unroll
            for (int q = 0; q < 4; q++) acc[i][j][q] = 0.f;

    const int lr4 = tid >> 2, lq4 = tid & 3;   // 64 rows x 4 quads (16B)

#define LOADV(c, st) do { \
    int k0 = (c) * 32; \
    _Pragma("unroll") \
    for (int i = 0; i < 2; i++) { \
        int r = lr4 + i * 64; \
        int ga = rowBase + r; if (ga >= M) ga = M - 1; \
        CP_ASYNC16(sb + ST_A(st) + r * SSTRB + lq4 * 16, \
                   A + (size_t)ga * S + k0 + lq4 * 8); \
        CP_ASYNC16(sb + ST_W(st) + r * SSTRB + lq4 * 16, \
                   W + (size_t)r * S + k0 + lq4 * 8); \
    } } while (0)

    LOADV(0, 0); CP_COMMIT();
    if (NC > 1) { LOADV(1, 1); }
    CP_COMMIT();

    const int a_row = lane & 15;
    const int a_sel = (lane >> 4) & 1;
    const int b_row = (lane & 7) + ((lane & 16) >> 1);
    const int b_sel = (lane >> 3) & 1;

    int stage = 0;
    for (int c = 0; c < NC; c++) {
        CP_WAIT1();
        __syncthreads();
        uint32_t abase = sb + ST_A(stage);
        uint32_t wbase = sb + ST_W(stage);
#pragma unroll
        for (int kh = 0; kh < 2; kh++) {
            uint32_t ar[2][4], br[8][2];
#pragma unroll
            for (int mi = 0; mi < 2; mi++) {
                uint32_t addr = abase + (mQ * 32 + mi * 16 + a_row) * SSTRB
                                + kh * 32 + a_sel * 16;
                LDMX4(ar[mi][0], ar[mi][1], ar[mi][2], ar[mi][3], addr);
            }
#pragma unroll
            for (int pi = 0; pi < 4; pi++) {
                uint32_t addr = wbase + (nH * 64 + pi * 16 + b_row) * SSTRB
                                + kh * 32 + b_sel * 16;
                LDMX4(br[2 * pi][0], br[2 * pi][1],
                      br[2 * pi + 1][0], br[2 * pi + 1][1], addr);
            }
#pragma unroll
            for (int mi = 0; mi < 2; mi++)
#pragma unroll
                for (int ni = 0; ni < 8; ni++)
                    MMA_FP16(acc[mi][ni], ar[mi], br[ni]);
        }
        // load chunk c+2 into stage (c+2)%3 == (c-1)%3: protected by the
        // barrier above (all warps have finished reading it at iter c-1).
        if (c + 2 < NC) {
            int st2 = stage + 2; if (st2 >= 3) st2 -= 3;
            LOADV(c + 2, st2);
        }
        CP_COMMIT();
        stage = (stage + 1 == 3) ? 0 : stage + 1;
    }
#undef LOADV

    const int g = lane >> 2, t = lane & 3;
#pragma unroll
    for (int mi = 0; mi < 2; mi++) {
        int r0 = rowBase + mQ * 32 + mi * 16 + g;
#pragma unroll
        for (int ni = 0; ni < 8; ni++) {
            int col = nH * 64 + ni * 8 + t * 2;
            float bx = 0.f, by2 = 0.f;
            if (bias) { bx = bias[col]; by2 = bias[col + 1]; }
            if (r0 < M) {
                __half2 v = __floats2half2_rn(acc[mi][ni][0] + bx, acc[mi][ni][1] + by2);
                *(__half2*)(C + (size_t)r0 * 128 + col) = v;
            }
            if (r0 + 8 < M) {
                __half2 v = __floats2half2_rn(acc[mi][ni][2] + bx, acc[mi][ni][3] + by2);
                *(__half2*)(C + (size_t)(r0 + 8) * 128 + col) = v;
            }
        }
    }
}

// ---------------------------------------------------------------------------
// Converts
// ---------------------------------------------------------------------------
__global__ void conv_feat3(const float* __restrict__ x0, const float* __restrict__ x1,
                           const float* __restrict__ x2, __half* __restrict__ outA)
{
    int row = blockIdx.x;
    int k = threadIdx.x * 4;
    if (k >= K1S) return;
    const float* src;
    if (row < N_ART) src = x0 + (size_t)row * FEATD;
    else if (row < N_ART + N_ENT) src = x1 + (size_t)(row - N_ART) * FEATD;
    else src = x2 + (size_t)(row - N_ART - N_ENT) * FEATD;
    __half h[4];
#pragma unroll
    for (int j = 0; j < 4; j++) {
        int kk = k + j;
        h[j] = __float2half((kk < FEATD) ? src[kk] : 0.f);
    }
    *(uint2*)(outA + (size_t)row * K1S + k) = *(uint2*)h;
}

__global__ void conv_fp16(const float* __restrict__ in,
                          __half* __restrict__ outA, int K, int S)
{
    int row = blockIdx.x;
    int k = threadIdx.x * 4;
    if (k >= S) return;
    const float* src = in + (size_t)row * K;
    __half h[4];
#pragma unroll
    for (int j = 0; j < 4; j++) {
        int kk = k + j;
        h[j] = __float2half((kk < K) ? src[kk] : 0.f);
    }
    *(uint2*)(outA + (size_t)row * S + k) = *(uint2*)h;
}

// ---------------------------------------------------------------------------
// CSR build
// ---------------------------------------------------------------------------
struct EdgePtrs { const int* e[5]; };

__global__ void count5_k(EdgePtrs ep, int* __restrict__ cnt, int E)
{
    int i = blockIdx.y;
    int e = blockIdx.x * blockDim.x + threadIdx.x;
    if (e < E) atomicAdd(&cnt[i * 100000 + ep.e[i][E + e]], 1);
}

__constant__ int c_dstN[5] = {100000, 50000, 50000, 50000, 100000};

__global__ void scan5_k(const int* __restrict__ cnt, int* __restrict__ off)
{
    __shared__ int sh[32];
    __shared__ int carry;
    int type = blockIdx.x;
    const int n = c_dstN[type];
    const int* c = cnt + type * 100000;
    int* o = off + type * 100032;
    int tid = threadIdx.x, lane = tid & 31, w = tid >> 5;
    if (tid == 0) carry = 0;
    __syncthreads();
    for (int base = 0; base < n; base += 1024) {
        int i = base + tid;
        int v = (i < n) ? c[i] : 0;
        int x = v;
#pragma unroll
        for (int d = 1; d < 32; d <<= 1) {
            int y = __shfl_up_sync(0xffffffffu, x, d);
            if (lane >= d) x += y;
        }
        if (lane == 31) sh[w] = x;
        __syncthreads();
        if (w == 0) {
            int s = sh[lane];
#pragma unroll
            for (int d = 1; d < 32; d <<= 1) {
                int y = __shfl_up_sync(0xffffffffu, s, d);
                if (lane >= d) s += y;
            }
            sh[lane] = s;
        }
        __syncthreads();
        int excl = x - v + (w > 0 ? sh[w - 1] : 0) + carry;
        if (i < n) o[i] = excl;
        __syncthreads();
        if (tid == 1023) carry = excl + v;
        __syncthreads();
    }
    if (tid == 0) o[n] = carry;
}

__global__ void fill5_k(EdgePtrs ep, const int* __restrict__ off, int* __restrict__ cursor,
                        int* __restrict__ srcA, int E)
{
    int i = blockIdx.y;
    int e = blockIdx.x * blockDim.x + threadIdx.x;
    if (e >= E) return;
    int d = ep.e[i][E + e];
    int pos = atomicAdd(&cursor[i * 100000 + d], 1);
    srcA[i * 200000 + off[i * 100032 + d] + pos] = ep.e[i][e];
}

// ---------------------------------------------------------------------------
// Fused gather + mean + lin_l + L2-normalize + relu + sum over <=2 edge types
// ---------------------------------------------------------------------------
__device__ __forceinline__ float4 ld_half4(const __half* p) {
    uint2 raw = *(const uint2*)p;
    __half2 h0 = *(__half2*)&raw.x;
    __half2 h1 = *(__half2*)&raw.y;
    float2 f0 = __half22float2(h0);
    float2 f1 = __half22float2(h1);
    return make_float4(f0.x, f0.y, f1.x, f1.y);
}

template<bool TWO, bool OUT_HALF>
__global__ void combine2(
    const __half* __restrict__ B0, const __half* __restrict__ P0,
    const int* __restrict__ off0, const int* __restrict__ src0,
    const __half* __restrict__ B1, const __half* __restrict__ P1,
    const int* __restrict__ off1, const int* __restrict__ src1,
    void* __restrict__ out, int n)
{
    int w = (blockIdx.x * blockDim.x + threadIdx.x) >> 5;
    int lane = threadIdx.x & 31;
    if (w >= n) return;
    size_t o = (size_t)w * HIDD + lane * 4;
    float4 r = make_float4(0.f, 0.f, 0.f, 0.f);

    {
        float4 b = ld_half4(B0 + o);
        int beg = __ldg(off0 + w), end = __ldg(off0 + w + 1);
        float4 a = make_float4(0.f, 0.f, 0.f, 0.f);
        for (int e = beg; e < end; e++) {
            int s = __ldg(src0 + e);
            float4 p = ld_half4(P0 + (size_t)s * HIDD + lane * 4);
            a.x += p.x; a.y += p.y; a.z += p.z; a.w += p.w;
        }
        float inv = 1.0f / fmaxf((float)(end - beg), 1.0f);
        float4 t;
        t.x = b.x + a.x * inv; t.y = b.y + a.y * inv;
        t.z = b.z + a.z * inv; t.w = b.w + a.w * inv;
        float ss = t.x * t.x + t.y * t.y + t.z * t.z + t.w * t.w;
#pragma unroll
        for (int sh = 16; sh; sh >>= 1) ss += __shfl_xor_sync(0xffffffffu, ss, sh);
        float sc = 1.0f / fmaxf(sqrtf(ss), 1e-12f);
        r.x += t.x * sc; r.y += t.y * sc; r.z += t.z * sc; r.w += t.w * sc;
    }
    if (TWO) {
        float4 b = ld_half4(B1 + o);
        int beg = __ldg(off1 + w), end = __ldg(off1 + w + 1);
        float4 a = make_float4(0.f, 0.f, 0.f, 0.f);
        for (int e = beg; e < end; e++) {
            int s = __ldg(src1 + e);
            float4 p = ld_half4(P1 + (size_t)s * HIDD + lane * 4);
            a.x += p.x; a.y += p.y; a.z += p.z; a.w += p.w;
        }
        float inv = 1.0f / fmaxf((float)(end - beg), 1.0f);
        float4 t;
        t.x = b.x + a.x * inv; t.y = b.y + a.y * inv;
        t.z = b.z + a.z * inv; t.w = b.w + a.w * inv;
        float ss = t.x * t.x + t.y * t.y + t.z * t.z + t.w * t.w;
#pragma unroll
        for (int sh = 16; sh; sh >>= 1) ss += __shfl_xor_sync(0xffffffffu, ss, sh);
        float sc = 1.0f / fmaxf(sqrtf(ss), 1e-12f);
        r.x += t.x * sc; r.y += t.y * sc; r.z += t.z * sc; r.w += t.w * sc;
    }
    r.x = fmaxf(r.x, 0.f); r.y = fmaxf(r.y, 0.f);
    r.z = fmaxf(r.z, 0.f); r.w = fmaxf(r.w, 0.f);

    if (OUT_HALF) {
        __half h[4];
        h[0] = __float2half(r.x); h[1] = __float2half(r.y);
        h[2] = __float2half(r.z); h[3] = __float2half(r.w);
        *(uint2*)((__half*)out + o) = *(uint2*)h;
    } else {
        *(float4*)((float*)out + o) = r;
    }
}

// ---------------------------------------------------------------------------
// SIMT GEMM for the 64-wide head
// ---------------------------------------------------------------------------
template<bool RELU_OUT>
__global__ __launch_bounds__(256) void gemm_tn(
    const float* __restrict__ A, const float* __restrict__ W,
    const float* __restrict__ bias, float* __restrict__ C,
    int M, int N, int K)
{
    __shared__ float As[8][128];
    __shared__ float Ws[8][128];
    const int tid = threadIdx.x;
    const int tx = tid & 15, ty = tid >> 4;
    const int rowBase = blockIdx.y * 128;

    float acc[8][8];
#pragma unroll
    for (int i = 0; i < 8; i++)
#pragma unroll
        for (int j = 0; j < 8; j++) acc[i][j] = 0.f;

    for (int k0 = 0; k0 < K; k0 += 8) {
#pragma unroll
        for (int t = 0; t < 4; t++) {
            int idx = tid + t * 256;
            int k = idx & 7, r = idx >> 3;
            int row = rowBase + r, kk = k0 + k;
            float v = 0.f;
            if (row < M && kk < K) v = A[(size_t)row * K + kk];
            As[k][r] = v;
        }
#pragma unroll
        for (int t = 0; t < 4; t++) {
            int idx = tid + t * 256;
            int k = idx & 7, c = idx >> 3;
            int kk = k0 + k;
            float v = 0.f;
            if (c < N && kk < K) v = W[(size_t)c * K + kk];
            Ws[k][c] = v;
        }
        __syncthreads();
#pragma unroll
        for (int k = 0; k < 8; k++) {
            float4 a0 = *(const float4*)&As[k][ty * 8];
            float4 a1 = *(const float4*)&As[k][ty * 8 + 4];
            float4 b0 = *(const float4*)&Ws[k][tx * 8];
            float4 b1 = *(const float4*)&Ws[k][tx * 8 + 4];
            float av[8] = {a0.x, a0.y, a0.z, a0.w, a1.x, a1.y, a1.z, a1.w};
            float bv[8] = {b0.x, b0.y, b0.z, b0.w, b1.x, b1.y, b1.z, b1.w};
#pragma unroll
            for (int i = 0; i < 8; i++)
#pragma unroll
                for (int j = 0; j < 8; j++) acc[i][j] += av[i] * bv[j];
        }
        __syncthreads();
    }

#pragma unroll
    for (int i = 0; i < 8; i++) {
        int row = rowBase + ty * 8 + i;
        if (row < M) {
#pragma unroll
            for (int j = 0; j < 8; j++) {
                int col = tx * 8 + j;
                if (col < N) {
                    float v = acc[i][j] + bias[col];
                    if (RELU_OUT) v = fmaxf(v, 0.f);
                    C[(size_t)row * N + col] = v;
                }
            }
        }
    }
}

__global__ void head2_k(const float* __restrict__ Z, const float* __restrict__ W2,
                        const float* __restrict__ b2, float* __restrict__ out, int n)
{
    int row = blockIdx.x * blockDim.x + threadIdx.x;
    if (row >= n) return;
    float acc0 = b2[0], acc1 = b2[1];
    const float* z = Z + (size_t)row * 64;
#pragma unroll
    for (int k = 0; k < 64; k++) {
        float zv = z[k];
        acc0 += zv * __ldg(W2 + k);
        acc1 += zv * __ldg(W2 + 64 + k);
    }
    out[row * 2 + 0] = acc0;
    out[row * 2 + 1] = acc1;
}

// ---------------------------------------------------------------------------
extern "C" void kernel_launch(void* const* d_in, const int* in_sizes, int n_in,
                              void* d_out_, int out_size)
{
    const float* x[3] = {(const float*)d_in[0], (const float*)d_in[1], (const float*)d_in[2]};
    const int nn[3] = {N_ART, N_ENT, N_FACT};
    const int* ei[5];
    for (int i = 0; i < 5; i++) ei[i] = (const int*)d_in[3 + i];
    const float* c1llw = (const float*)d_in[8];
    const float* c1llb = (const float*)d_in[9];
    const float* c1lrw = (const float*)d_in[10];
    const float* c2llw = (const float*)d_in[11];
    const float* c2llb = (const float*)d_in[12];
    const float* c2lrw = (const float*)d_in[13];
    const float* hw1 = (const float*)d_in[14];
    const float* hb1 = (const float*)d_in[15];
    const float* hw2 = (const float*)d_in[16];
    const float* hb2 = (const float*)d_in[17];
    float* out = (float*)d_out_;

    static const size_t BOFF[5] = {0, 100000, 150000, 200000, 250000};
    static const size_t POFF[5] = {0, 50000, 100000, 200000, 300000};

    float *Z;
    __half *B5, *P5, *Xh, *H1h, *W1L, *W1R, *W2L, *W2R;
    int *CUR, *OFFS, *SRCA;
    cudaGetSymbolAddress((void**)&B5, g_B5);
    cudaGetSymbolAddress((void**)&P5, g_P5);
    cudaGetSymbolAddress((void**)&Z, g_z);
    cudaGetSymbolAddress((void**)&Xh, g_Xh);
    cudaGetSymbolAddress((void**)&H1h, g_H1h);
    cudaGetSymbolAddress((void**)&W1L, g_W1L);
    cudaGetSymbolAddress((void**)&W1R, g_W1R);
    cudaGetSymbolAddress((void**)&W2L, g_W2L);
    cudaGetSymbolAddress((void**)&W2R, g_W2R);
    cudaGetSymbolAddress((void**)&CUR, g_cursor);
    cudaGetSymbolAddress((void**)&OFFS, g_off);
    cudaGetSymbolAddress((void**)&SRCA, g_srcA);

    cudaFuncSetAttribute(gemm_fp16_1p, cudaFuncAttributeMaxDynamicSharedMemorySize, SMEM_V);

    const size_t XHB[3] = {0, (size_t)N_ART * K1S, (size_t)(N_ART + N_ENT) * K1S};
    const size_t R0[3] = {0, (size_t)N_ART, (size_t)(N_ART + N_ENT)};

    __half* h1p[3] = {H1h, H1h + (size_t)N_ART * HIDD, H1h + (size_t)(N_ART + N_ENT) * HIDD};
    float* h2p[3] = {out + 100000,
                     out + 100000 + (size_t)N_ART * HIDD,
                     out + 100000 + (size_t)(N_ART + N_ENT) * HIDD};

    const int NBLK[3] = {3, 4, 3};
    const int LLe[3][2] = {{2, -1}, {0, 4}, {1, 3}};
    const int LRe[3][2] = {{0, 1}, {2, 3}, {4, -1}};

    const size_t WB1B = (size_t)128 * K1S * 2;
    const size_t WB2B = (size_t)128 * K2S * 2;

    auto make_outs = [&](int layer, int t) {
        MultiOut p;
        const char* WL = layer ? (const char*)W2L : (const char*)W1L;
        const char* WR = layer ? (const char*)W2R : (const char*)W1R;
        const float* bb = layer ? c2llb : c1llb;
        const size_t WBB = layer ? WB2B : WB1B;
        int nb = 0;
        for (int j = 0; j < 2; j++) {
            int e = LLe[t][j];
            if (e < 0) break;
            p.W[nb] = WL + (size_t)e * WBB;
            p.bias[nb] = bb + e * HIDD;
            p.C[nb] = B5 + BOFF[e] * HIDD;
            nb++;
        }
        for (int j = 0; j < 2; j++) {
            int e = LRe[t][j];
            if (e < 0) break;
            p.W[nb] = WR + (size_t)e * WBB;
            p.bias[nb] = nullptr;
            p.C[nb] = P5 + POFF[e] * HIDD;
            nb++;
        }
        return p;
    };

    // --- launches 0-2: converts needed for layer-1 GEMMs ---
    conv_feat3<<<200000, 256>>>(x[0], x[1], x[2], Xh);
    conv_fp16<<<640, 256>>>(c1llw, W1L, FEATD, K1S);
    conv_fp16<<<640, 256>>>(c1lrw, W1R, FEATD, K1S);

    // --- launches 3-5: layer-1 GEMMs (ncu capture lands here) ---
    for (int t = 1; t >= 0; t--) {
        MultiOut p = make_outs(0, t);
        gemm_fp16_1p<<<dim3(NBLK[t], (nn[t] + 127) / 128), 256, SMEM_V>>>(
            Xh + XHB[t], p, nn[t], K1S);
    }
    {
        MultiOut p = make_outs(0, 2);
        gemm_fp16_1p<<<dim3(NBLK[2], (nn[2] + 127) / 128), 256, SMEM_V>>>(
            Xh + XHB[2], p, nn[2], K1S);
    }

    // --- CSR build + W2 converts ---
    EdgePtrs ep;
    for (int i = 0; i < 5; i++) ep.e[i] = ei[i];
    cudaMemsetAsync(CUR, 0, 500000 * sizeof(int));
    count5_k<<<dim3((NEDGE + 255) / 256, 5), 256>>>(ep, CUR, NEDGE);
    scan5_k<<<5, 1024>>>(CUR, OFFS);
    cudaMemsetAsync(CUR, 0, 500000 * sizeof(int));
    fill5_k<<<dim3((NEDGE + 255) / 256, 5), 256>>>(ep, OFFS, CUR, SRCA, NEDGE);
    conv_fp16<<<640, 32>>>(c2llw, W2L, HIDD, K2S);
    conv_fp16<<<640, 32>>>(c2lrw, W2R, HIDD, K2S);

    // --- layer-1 combines: relu fused, fp16 out directly into H1h ---
    combine2<false, true><<<(N_ART + 7) / 8, 256>>>(
        B5 + BOFF[2] * HIDD, P5 + POFF[2] * HIDD, OFFS + 2 * 100032, SRCA + 2 * 200000,
        nullptr, nullptr, nullptr, nullptr, h1p[0], N_ART);
    combine2<true, true><<<(N_ENT + 7) / 8, 256>>>(
        B5 + BOFF[0] * HIDD, P5 + POFF[0] * HIDD, OFFS + 0 * 100032, SRCA + 0 * 200000,
        B5 + BOFF[4] * HIDD, P5 + POFF[4] * HIDD, OFFS + 4 * 100032, SRCA + 4 * 200000,
        h1p[1], N_ENT);
    combine2<true, true><<<(N_FACT + 7) / 8, 256>>>(
        B5 + BOFF[1] * HIDD, P5 + POFF[1] * HIDD, OFFS + 1 * 100032, SRCA + 1 * 200000,
        B5 + BOFF[3] * HIDD, P5 + POFF[3] * HIDD, OFFS + 3 * 100032, SRCA + 3 * 200000,
        h1p[2], N_FACT);

    // --- layer-2 GEMMs (fp16 single-pass) ---
    for (int t = 1; t >= 0; t--) {
        MultiOut p = make_outs(1, t);
        gemm_fp16_1p<<<dim3(NBLK[t], (nn[t] + 127) / 128), 256, SMEM_V>>>(
            H1h + R0[t] * K2S, p, nn[t], K2S);
    }
    {
        MultiOut p = make_outs(1, 2);
        gemm_fp16_1p<<<dim3(NBLK[2], (nn[2] + 127) / 128), 256, SMEM_V>>>(
            H1h + R0[2] * K2S, p, nn[2], K2S);
    }

    // --- layer-2 combines: relu fused, fp32 out (d_out dtype) ---
    combine2<false, false><<<(N_ART + 7) / 8, 256>>>(
        B5 + BOFF[2] * HIDD, P5 + POFF[2] * HIDD, OFFS + 2 * 100032, SRCA + 2 * 200000,
        nullptr, nullptr, nullptr, nullptr, h2p[0], N_ART);
    combine2<true, false><<<(N_ENT + 7) / 8, 256>>>(
        B5 + BOFF[0] * HIDD, P5 + POFF[0] * HIDD, OFFS + 0 * 100032, SRCA + 0 * 200000,
        B5 + BOFF[4] * HIDD, P5 + POFF[4] * HIDD, OFFS + 4 * 100032, SRCA + 4 * 200000,
        h2p[1], N_ENT);
    combine2<true, false><<<(N_FACT + 7) / 8, 256>>>(
        B5 + BOFF[1] * HIDD, P5 + POFF[1] * HIDD, OFFS + 1 * 100032, SRCA + 1 * 200000,
        B5 + BOFF[3] * HIDD, P5 + POFF[3] * HIDD, OFFS + 3 * 100032, SRCA + 3 * 200000,
        h2p[2], N_FACT);

    // --- head MLP ---
    gemm_tn<true><<<dim3(1, (N_ART + 127) / 128), 256>>>(
        out + 100000, hw1, hb1, Z, N_ART, 64, HIDD);
    head2_k<<<(N_ART + 255) / 256, 256>>>(Z, hw2, hb2, out, N_ART);
}

// round 17
// speedup vs baseline: 1.1673x; 1.0297x over previous
#include <cuda_runtime.h>
#include <cuda_fp16.h>
#include <math.h>
#include <stdint.h>

#define N_ART 50000
#define N_ENT 100000
#define N_FACT 50000
#define NEDGE 200000
#define FEATD 769
#define HIDD 128

#define K1S 800
#define K2S 128

// ---------------------------------------------------------------------------
// Scratch
// ---------------------------------------------------------------------------
__device__ __half g_B5[44800000];               // 5 lin_l outputs (dst rows), fp16
__device__ __half g_P5[44800000];               // 5 lin_r outputs (src rows), fp16
__device__ float g_z[3200000];
__device__ __half g_Xh[160000000];              // fp16 features: 200k x 800 (art|ent|fact)
__device__ __half g_H1h[25600000];              // fp16 relu(h1): 200k x 128
__device__ __half g_W1L[512000];                // c1 lin_l fp16: 640 x 800
__device__ __half g_W1R[512000];
__device__ __half g_W2L[81920];                 // c2 lin_l fp16: 640 x 128
__device__ __half g_W2R[81920];
__device__ int g_cursor[500000];
__device__ int g_off[500160];                   // per-type CSR offsets (stride 100032)
__device__ int g_srcA[1000000];                 // per-type CSR src lists (stride 200000)

// ---------------------------------------------------------------------------
__device__ __forceinline__ uint32_t smem_u32(const void* p) {
    uint32_t a;
    asm("{ .reg .u64 t; cvta.to.shared.u64 t, %1; cvt.u32.u64 %0, t; }"
        : "=r"(a) : "l"(p));
    return a;
}

#define CP_ASYNC16(dst, src) \
    asm volatile("cp.async.cg.shared.global [%0], [%1], 16;" :: "r"(dst), "l"(src))
#define CP_COMMIT() asm volatile("cp.async.commit_group;" ::: "memory")
#define CP_WAIT1()  asm volatile("cp.async.wait_group 1;" ::: "memory")

#define SSTRB 80

#define LDMX4(r0, r1, r2, r3, addr) \
    asm volatile("ldmatrix.sync.aligned.m8n8.x4.shared.b16 {%0,%1,%2,%3}, [%4];" \
                 : "=r"(r0), "=r"(r1), "=r"(r2), "=r"(r3) : "r"(addr))

#define MMA_FP16(acc, a, b) \
    asm volatile("mma.sync.aligned.m16n8k16.row.col.f32.f16.f16.f32 " \
                 "{%0,%1,%2,%3}, {%4,%5,%6,%7}, {%8,%9}, {%0,%1,%2,%3};" \
                 : "+f"((acc)[0]), "+f"((acc)[1]), "+f"((acc)[2]), "+f"((acc)[3]) \
                 : "r"((a)[0]), "r"((a)[1]), "r"((a)[2]), "r"((a)[3]), \
                   "r"((b)[0]), "r"((b)[1]))

// ---------------------------------------------------------------------------
// Batched fp16 GEMM over 3 node types in one launch.
// Per (type t, weight block b, row tile x): C[t][b][x*128.., :128] =
//   A[t][x*128.., :S] @ W[t][b]^T (+bias), fp16 out.
// 128x128 CTA tile, 32x64 warp tiles, 3-stage cp.async, 1 barrier/chunk.
// ---------------------------------------------------------------------------
struct GemmBatch {
    const __half* A[3];
    int M[3];
    int nblk[3];
    int ctaStart[4];       // cumulative CTA counts per type
    const __half* W[3][4];
    const float* bias[3][4];
    __half* C[3][4];
};

#define ST_A(s) ((s) * 10240)
#define ST_W(s) (30720 + (s) * 10240)
#define SMEM_V  61440

__global__ __launch_bounds__(256, 2) void gemm_batch(GemmBatch gb, int S)
{
    extern __shared__ char sm[];
    const uint32_t sb = smem_u32(sm);
    const int tid = threadIdx.x, lane = tid & 31, warp = tid >> 5;
    const int mQ = warp >> 1, nH = warp & 1;

    const int bid = blockIdx.x;
    const int t = (bid >= gb.ctaStart[1]) + (bid >= gb.ctaStart[2]);
    const int local = bid - gb.ctaStart[t];
    const int nb = gb.nblk[t];
    const int by = local % nb;
    const int rowBase = (local / nb) * 128;
    const __half* __restrict__ A = gb.A[t];
    const int M = gb.M[t];
    const __half* __restrict__ W = gb.W[t][by];
    const float* __restrict__ bias = gb.bias[t][by];
    __half* __restrict__ C = gb.C[t][by];
    const int NC = S >> 5;

    float acc[2][8][4];
#pragma unroll
    for (int i = 0; i < 2; i++)
#pragma unroll
        for (int j = 0; j < 8; j++)
#pragma unroll
            for (int q = 0; q < 4; q++) acc[i][j][q] = 0.f;

    const int lr4 = tid >> 2, lq4 = tid & 3;

#define LOADV(c, st) do { \
    int k0 = (c) * 32; \
    _Pragma("unroll") \
    for (int i = 0; i < 2; i++) { \
        int r = lr4 + i * 64; \
        int ga = rowBase + r; if (ga >= M) ga = M - 1; \
        CP_ASYNC16(sb + ST_A(st) + r * SSTRB + lq4 * 16, \
                   A + (size_t)ga * S + k0 + lq4 * 8); \
        CP_ASYNC16(sb + ST_W(st) + r * SSTRB + lq4 * 16, \
                   W + (size_t)r * S + k0 + lq4 * 8); \
    } } while (0)

    LOADV(0, 0); CP_COMMIT();
    if (NC > 1) { LOADV(1, 1); }
    CP_COMMIT();

    const int a_row = lane & 15;
    const int a_sel = (lane >> 4) & 1;
    const int b_row = (lane & 7) + ((lane & 16) >> 1);
    const int b_sel = (lane >> 3) & 1;

    int stage = 0;
    for (int c = 0; c < NC; c++) {
        CP_WAIT1();
        __syncthreads();
        uint32_t abase = sb + ST_A(stage);
        uint32_t wbase = sb + ST_W(stage);
#pragma unroll
        for (int kh = 0; kh < 2; kh++) {
            uint32_t ar[2][4], br[8][2];
#pragma unroll
            for (int mi = 0; mi < 2; mi++) {
                uint32_t addr = abase + (mQ * 32 + mi * 16 + a_row) * SSTRB
                                + kh * 32 + a_sel * 16;
                LDMX4(ar[mi][0], ar[mi][1], ar[mi][2], ar[mi][3], addr);
            }
#pragma unroll
            for (int pi = 0; pi < 4; pi++) {
                uint32_t addr = wbase + (nH * 64 + pi * 16 + b_row) * SSTRB
                                + kh * 32 + b_sel * 16;
                LDMX4(br[2 * pi][0], br[2 * pi][1],
                      br[2 * pi + 1][0], br[2 * pi + 1][1], addr);
            }
#pragma unroll
            for (int mi = 0; mi < 2; mi++)
#pragma unroll
                for (int ni = 0; ni < 8; ni++)
                    MMA_FP16(acc[mi][ni], ar[mi], br[ni]);
        }
        if (c + 2 < NC) {
            int st2 = stage + 2; if (st2 >= 3) st2 -= 3;
            LOADV(c + 2, st2);
        }
        CP_COMMIT();
        stage = (stage + 1 == 3) ? 0 : stage + 1;
    }
#undef LOADV

    const int g = lane >> 2, tq = lane & 3;
#pragma unroll
    for (int mi = 0; mi < 2; mi++) {
        int r0 = rowBase + mQ * 32 + mi * 16 + g;
#pragma unroll
        for (int ni = 0; ni < 8; ni++) {
            int col = nH * 64 + ni * 8 + tq * 2;
            float bx = 0.f, by2 = 0.f;
            if (bias) { bx = bias[col]; by2 = bias[col + 1]; }
            if (r0 < M) {
                __half2 v = __floats2half2_rn(acc[mi][ni][0] + bx, acc[mi][ni][1] + by2);
                *(__half2*)(C + (size_t)r0 * 128 + col) = v;
            }
            if (r0 + 8 < M) {
                __half2 v = __floats2half2_rn(acc[mi][ni][2] + bx, acc[mi][ni][3] + by2);
                *(__half2*)(C + (size_t)(r0 + 8) * 128 + col) = v;
            }
        }
    }
}

// ---------------------------------------------------------------------------
// Converts
// ---------------------------------------------------------------------------
__global__ void conv_feat3(const float* __restrict__ x0, const float* __restrict__ x1,
                           const float* __restrict__ x2, __half* __restrict__ outA)
{
    int row = blockIdx.x;
    int k = threadIdx.x * 4;
    if (k >= K1S) return;
    const float* src;
    if (row < N_ART) src = x0 + (size_t)row * FEATD;
    else if (row < N_ART + N_ENT) src = x1 + (size_t)(row - N_ART) * FEATD;
    else src = x2 + (size_t)(row - N_ART - N_ENT) * FEATD;
    __half h[4];
#pragma unroll
    for (int j = 0; j < 4; j++) {
        int kk = k + j;
        h[j] = __float2half((kk < FEATD) ? src[kk] : 0.f);
    }
    *(uint2*)(outA + (size_t)row * K1S + k) = *(uint2*)h;
}

__global__ void conv_fp16(const float* __restrict__ in,
                          __half* __restrict__ outA, int K, int S)
{
    int row = blockIdx.x;
    int k = threadIdx.x * 4;
    if (k >= S) return;
    const float* src = in + (size_t)row * K;
    __half h[4];
#pragma unroll
    for (int j = 0; j < 4; j++) {
        int kk = k + j;
        h[j] = __float2half((kk < K) ? src[kk] : 0.f);
    }
    *(uint2*)(outA + (size_t)row * S + k) = *(uint2*)h;
}

// ---------------------------------------------------------------------------
// CSR build
// ---------------------------------------------------------------------------
struct EdgePtrs { const int* e[5]; };

__global__ void count5_k(EdgePtrs ep, int* __restrict__ cnt, int E)
{
    int i = blockIdx.y;
    int e = blockIdx.x * blockDim.x + threadIdx.x;
    if (e < E) atomicAdd(&cnt[i * 100000 + ep.e[i][E + e]], 1);
}

__constant__ int c_dstN[5] = {100000, 50000, 50000, 50000, 100000};

__global__ void scan5_k(const int* __restrict__ cnt, int* __restrict__ off)
{
    __shared__ int sh[32];
    __shared__ int carry;
    int type = blockIdx.x;
    const int n = c_dstN[type];
    const int* c = cnt + type * 100000;
    int* o = off + type * 100032;
    int tid = threadIdx.x, lane = tid & 31, w = tid >> 5;
    if (tid == 0) carry = 0;
    __syncthreads();
    for (int base = 0; base < n; base += 1024) {
        int i = base + tid;
        int v = (i < n) ? c[i] : 0;
        int x = v;
#pragma unroll
        for (int d = 1; d < 32; d <<= 1) {
            int y = __shfl_up_sync(0xffffffffu, x, d);
            if (lane >= d) x += y;
        }
        if (lane == 31) sh[w] = x;
        __syncthreads();
        if (w == 0) {
            int s = sh[lane];
#pragma unroll
            for (int d = 1; d < 32; d <<= 1) {
                int y = __shfl_up_sync(0xffffffffu, s, d);
                if (lane >= d) s += y;
            }
            sh[lane] = s;
        }
        __syncthreads();
        int excl = x - v + (w > 0 ? sh[w - 1] : 0) + carry;
        if (i < n) o[i] = excl;
        __syncthreads();
        if (tid == 1023) carry = excl + v;
        __syncthreads();
    }
    if (tid == 0) o[n] = carry;
}

__global__ void fill5_k(EdgePtrs ep, const int* __restrict__ off, int* __restrict__ cursor,
                        int* __restrict__ srcA, int E)
{
    int i = blockIdx.y;
    int e = blockIdx.x * blockDim.x + threadIdx.x;
    if (e >= E) return;
    int d = ep.e[i][E + e];
    int pos = atomicAdd(&cursor[i * 100000 + d], 1);
    srcA[i * 200000 + off[i * 100032 + d] + pos] = ep.e[i][e];
}

// ---------------------------------------------------------------------------
// Batched fused combine over all 3 node types in one launch.
// ---------------------------------------------------------------------------
__device__ __forceinline__ float4 ld_half4(const __half* p) {
    uint2 raw = *(const uint2*)p;
    __half2 h0 = *(__half2*)&raw.x;
    __half2 h1 = *(__half2*)&raw.y;
    float2 f0 = __half22float2(h0);
    float2 f1 = __half22float2(h1);
    return make_float4(f0.x, f0.y, f1.x, f1.y);
}

struct CombBatch {
    const __half* B0[3]; const __half* P0[3];
    const int* off0[3];  const int* src0[3];
    const __half* B1[3]; const __half* P1[3];
    const int* off1[3];  const int* src1[3];
    void* out[3];
    int rowStart[4];     // 0, 50000, 150000, 200000
};

template<bool OUT_HALF>
__global__ void combine_batch(CombBatch cb)
{
    int w = (blockIdx.x * blockDim.x + threadIdx.x) >> 5;
    int lane = threadIdx.x & 31;
    if (w >= cb.rowStart[3]) return;
    int t = (w >= cb.rowStart[1]) + (w >= cb.rowStart[2]);
    int row = w - cb.rowStart[t];
    size_t o = (size_t)row * HIDD + lane * 4;
    float4 r = make_float4(0.f, 0.f, 0.f, 0.f);

    {
        float4 b = ld_half4(cb.B0[t] + o);
        const int* off = cb.off0[t];
        const int* srcl = cb.src0[t];
        const __half* P = cb.P0[t];
        int beg = __ldg(off + row), end = __ldg(off + row + 1);
        float4 a = make_float4(0.f, 0.f, 0.f, 0.f);
        for (int e = beg; e < end; e++) {
            int s = __ldg(srcl + e);
            float4 p = ld_half4(P + (size_t)s * HIDD + lane * 4);
            a.x += p.x; a.y += p.y; a.z += p.z; a.w += p.w;
        }
        float inv = 1.0f / fmaxf((float)(end - beg), 1.0f);
        float4 tt;
        tt.x = b.x + a.x * inv; tt.y = b.y + a.y * inv;
        tt.z = b.z + a.z * inv; tt.w = b.w + a.w * inv;
        float ss = tt.x * tt.x + tt.y * tt.y + tt.z * tt.z + tt.w * tt.w;
#pragma unroll
        for (int sh = 16; sh; sh >>= 1) ss += __shfl_xor_sync(0xffffffffu, ss, sh);
        float sc = 1.0f / fmaxf(sqrtf(ss), 1e-12f);
        r.x += tt.x * sc; r.y += tt.y * sc; r.z += tt.z * sc; r.w += tt.w * sc;
    }
    if (cb.src1[t]) {
        float4 b = ld_half4(cb.B1[t] + o);
        const int* off = cb.off1[t];
        const int* srcl = cb.src1[t];
        const __half* P = cb.P1[t];
        int beg = __ldg(off + row), end = __ldg(off + row + 1);
        float4 a = make_float4(0.f, 0.f, 0.f, 0.f);
        for (int e = beg; e < end; e++) {
            int s = __ldg(srcl + e);
            float4 p = ld_half4(P + (size_t)s * HIDD + lane * 4);
            a.x += p.x; a.y += p.y; a.z += p.z; a.w += p.w;
        }
        float inv = 1.0f / fmaxf((float)(end - beg), 1.0f);
        float4 tt;
        tt.x = b.x + a.x * inv; tt.y = b.y + a.y * inv;
        tt.z = b.z + a.z * inv; tt.w = b.w + a.w * inv;
        float ss = tt.x * tt.x + tt.y * tt.y + tt.z * tt.z + tt.w * tt.w;
#pragma unroll
        for (int sh = 16; sh; sh >>= 1) ss += __shfl_xor_sync(0xffffffffu, ss, sh);
        float sc = 1.0f / fmaxf(sqrtf(ss), 1e-12f);
        r.x += tt.x * sc; r.y += tt.y * sc; r.z += tt.z * sc; r.w += tt.w * sc;
    }
    r.x = fmaxf(r.x, 0.f); r.y = fmaxf(r.y, 0.f);
    r.z = fmaxf(r.z, 0.f); r.w = fmaxf(r.w, 0.f);

    if (OUT_HALF) {
        __half h[4];
        h[0] = __float2half(r.x); h[1] = __float2half(r.y);
        h[2] = __float2half(r.z); h[3] = __float2half(r.w);
        *(uint2*)((__half*)cb.out[t] + o) = *(uint2*)h;
    } else {
        *(float4*)((float*)cb.out[t] + o) = r;
    }
}

// ---------------------------------------------------------------------------
// SIMT GEMM for the 64-wide head
// ---------------------------------------------------------------------------
template<bool RELU_OUT>
__global__ __launch_bounds__(256) void gemm_tn(
    const float* __restrict__ A, const float* __restrict__ W,
    const float* __restrict__ bias, float* __restrict__ C,
    int M, int N, int K)
{
    __shared__ float As[8][128];
    __shared__ float Ws[8][128];
    const int tid = threadIdx.x;
    const int tx = tid & 15, ty = tid >> 4;
    const int rowBase = blockIdx.y * 128;

    float acc[8][8];
#pragma unroll
    for (int i = 0; i < 8; i++)
#pragma unroll
        for (int j = 0; j < 8; j++) acc[i][j] = 0.f;

    for (int k0 = 0; k0 < K; k0 += 8) {
#pragma unroll
        for (int t = 0; t < 4; t++) {
            int idx = tid + t * 256;
            int k = idx & 7, r = idx >> 3;
            int row = rowBase + r, kk = k0 + k;
            float v = 0.f;
            if (row < M && kk < K) v = A[(size_t)row * K + kk];
            As[k][r] = v;
        }
#pragma unroll
        for (int t = 0; t < 4; t++) {
            int idx = tid + t * 256;
            int k = idx & 7, c = idx >> 3;
            int kk = k0 + k;
            float v = 0.f;
            if (c < N && kk < K) v = W[(size_t)c * K + kk];
            Ws[k][c] = v;
        }
        __syncthreads();
#pragma unroll
        for (int k = 0; k < 8; k++) {
            float4 a0 = *(const float4*)&As[k][ty * 8];
            float4 a1 = *(const float4*)&As[k][ty * 8 + 4];
            float4 b0 = *(const float4*)&Ws[k][tx * 8];
            float4 b1 = *(const float4*)&Ws[k][tx * 8 + 4];
            float av[8] = {a0.x, a0.y, a0.z, a0.w, a1.x, a1.y, a1.z, a1.w};
            float bv[8] = {b0.x, b0.y, b0.z, b0.w, b1.x, b1.y, b1.z, b1.w};
#pragma unroll
            for (int i = 0; i < 8; i++)
#pragma unroll
                for (int j = 0; j < 8; j++) acc[i][j] += av[i] * bv[j];
        }
        __syncthreads();
    }

#pragma unroll
    for (int i = 0; i < 8; i++) {
        int row = rowBase + ty * 8 + i;
        if (row < M) {
#pragma unroll
            for (int j = 0; j < 8; j++) {
                int col = tx * 8 + j;
                if (col < N) {
                    float v = acc[i][j] + bias[col];
                    if (RELU_OUT) v = fmaxf(v, 0.f);
                    C[(size_t)row * N + col] = v;
                }
            }
        }
    }
}

__global__ void head2_k(const float* __restrict__ Z, const float* __restrict__ W2,
                        const float* __restrict__ b2, float* __restrict__ out, int n)
{
    int row = blockIdx.x * blockDim.x + threadIdx.x;
    if (row >= n) return;
    float acc0 = b2[0], acc1 = b2[1];
    const float* z = Z + (size_t)row * 64;
#pragma unroll
    for (int k = 0; k < 64; k++) {
        float zv = z[k];
        acc0 += zv * __ldg(W2 + k);
        acc1 += zv * __ldg(W2 + 64 + k);
    }
    out[row * 2 + 0] = acc0;
    out[row * 2 + 1] = acc1;
}

// ---------------------------------------------------------------------------
extern "C" void kernel_launch(void* const* d_in, const int* in_sizes, int n_in,
                              void* d_out_, int out_size)
{
    const float* x[3] = {(const float*)d_in[0], (const float*)d_in[1], (const float*)d_in[2]};
    const int nn[3] = {N_ART, N_ENT, N_FACT};
    const int* ei[5];
    for (int i = 0; i < 5; i++) ei[i] = (const int*)d_in[3 + i];
    const float* c1llw = (const float*)d_in[8];
    const float* c1llb = (const float*)d_in[9];
    const float* c1lrw = (const float*)d_in[10];
    const float* c2llw = (const float*)d_in[11];
    const float* c2llb = (const float*)d_in[12];
    const float* c2lrw = (const float*)d_in[13];
    const float* hw1 = (const float*)d_in[14];
    const float* hb1 = (const float*)d_in[15];
    const float* hw2 = (const float*)d_in[16];
    const float* hb2 = (const float*)d_in[17];
    float* out = (float*)d_out_;

    static const size_t BOFF[5] = {0, 100000, 150000, 200000, 250000};
    static const size_t POFF[5] = {0, 50000, 100000, 200000, 300000};

    float *Z;
    __half *B5, *P5, *Xh, *H1h, *W1L, *W1R, *W2L, *W2R;
    int *CUR, *OFFS, *SRCA;
    cudaGetSymbolAddress((void**)&B5, g_B5);
    cudaGetSymbolAddress((void**)&P5, g_P5);
    cudaGetSymbolAddress((void**)&Z, g_z);
    cudaGetSymbolAddress((void**)&Xh, g_Xh);
    cudaGetSymbolAddress((void**)&H1h, g_H1h);
    cudaGetSymbolAddress((void**)&W1L, g_W1L);
    cudaGetSymbolAddress((void**)&W1R, g_W1R);
    cudaGetSymbolAddress((void**)&W2L, g_W2L);
    cudaGetSymbolAddress((void**)&W2R, g_W2R);
    cudaGetSymbolAddress((void**)&CUR, g_cursor);
    cudaGetSymbolAddress((void**)&OFFS, g_off);
    cudaGetSymbolAddress((void**)&SRCA, g_srcA);

    cudaFuncSetAttribute(gemm_batch, cudaFuncAttributeMaxDynamicSharedMemorySize, SMEM_V);

    const size_t XHB[3] = {0, (size_t)N_ART * K1S, (size_t)(N_ART + N_ENT) * K1S};
    const size_t R0[3] = {0, (size_t)N_ART, (size_t)(N_ART + N_ENT)};

    __half* h1p[3] = {H1h, H1h + (size_t)N_ART * HIDD, H1h + (size_t)(N_ART + N_ENT) * HIDD};
    float* h2p[3] = {out + 100000,
                     out + 100000 + (size_t)N_ART * HIDD,
                     out + 100000 + (size_t)(N_ART + N_ENT) * HIDD};

    const int NBLK[3] = {3, 4, 3};
    const int LLe[3][2] = {{2, -1}, {0, 4}, {1, 3}};
    const int LRe[3][2] = {{0, 1}, {2, 3}, {4, -1}};

    const size_t WB1 = (size_t)128 * K1S;   // elements
    const size_t WB2 = (size_t)128 * K2S;

    auto make_batch = [&](int layer) {
        GemmBatch gb;
        const __half* WL = layer ? W2L : W1L;
        const __half* WR = layer ? W2R : W1R;
        const float* bb = layer ? c2llb : c1llb;
        const size_t WB = layer ? WB2 : WB1;
        int cum = 0;
        for (int t = 0; t < 3; t++) {
            gb.A[t] = layer ? (H1h + R0[t] * K2S) : (Xh + XHB[t]);
            gb.M[t] = nn[t];
            gb.nblk[t] = NBLK[t];
            gb.ctaStart[t] = cum;
            cum += NBLK[t] * ((nn[t] + 127) / 128);
            int nb = 0;
            for (int j = 0; j < 2; j++) {
                int e = LLe[t][j];
                if (e < 0) break;
                gb.W[t][nb] = WL + (size_t)e * WB;
                gb.bias[t][nb] = bb + e * HIDD;
                gb.C[t][nb] = B5 + BOFF[e] * HIDD;
                nb++;
            }
            for (int j = 0; j < 2; j++) {
                int e = LRe[t][j];
                if (e < 0) break;
                gb.W[t][nb] = WR + (size_t)e * WB;
                gb.bias[t][nb] = nullptr;
                gb.C[t][nb] = P5 + POFF[e] * HIDD;
                nb++;
            }
            for (; nb < 4; nb++) {
                gb.W[t][nb] = nullptr; gb.bias[t][nb] = nullptr; gb.C[t][nb] = nullptr;
            }
        }
        gb.ctaStart[3] = cum;
        return gb;
    };

    auto make_comb = [&](int layer) {
        CombBatch cb;
        // art<-e2, ent<-e0+e4, fact<-e1+e3
        const int E0[3] = {2, 0, 1};
        const int E1[3] = {-1, 4, 3};
        int cum = 0;
        for (int t = 0; t < 3; t++) {
            int e0 = E0[t], e1 = E1[t];
            cb.B0[t] = B5 + BOFF[e0] * HIDD;
            cb.P0[t] = P5 + POFF[e0] * HIDD;
            cb.off0[t] = OFFS + e0 * 100032;
            cb.src0[t] = SRCA + e0 * 200000;
            if (e1 >= 0) {
                cb.B1[t] = B5 + BOFF[e1] * HIDD;
                cb.P1[t] = P5 + POFF[e1] * HIDD;
                cb.off1[t] = OFFS + e1 * 100032;
                cb.src1[t] = SRCA + e1 * 200000;
            } else {
                cb.B1[t] = nullptr; cb.P1[t] = nullptr;
                cb.off1[t] = nullptr; cb.src1[t] = nullptr;
            }
            cb.out[t] = layer ? (void*)h2p[t] : (void*)h1p[t];
            cb.rowStart[t] = cum;
            cum += nn[t];
        }
        cb.rowStart[3] = cum;
        return cb;
    };

    // --- launches 0-4: converts ---
    conv_feat3<<<200000, 256>>>(x[0], x[1], x[2], Xh);
    conv_fp16<<<640, 256>>>(c1llw, W1L, FEATD, K1S);
    conv_fp16<<<640, 256>>>(c1lrw, W1R, FEATD, K1S);
    conv_fp16<<<640, 32>>>(c2llw, W2L, HIDD, K2S);
    conv_fp16<<<640, 32>>>(c2lrw, W2R, HIDD, K2S);

    // --- launch 5: merged layer-1 GEMM (ncu capture) ---
    {
        GemmBatch gb = make_batch(0);
        gemm_batch<<<gb.ctaStart[3], 256, SMEM_V>>>(gb, K1S);
    }

    // --- CSR build ---
    EdgePtrs ep;
    for (int i = 0; i < 5; i++) ep.e[i] = ei[i];
    cudaMemsetAsync(CUR, 0, 500000 * sizeof(int));
    count5_k<<<dim3((NEDGE + 255) / 256, 5), 256>>>(ep, CUR, NEDGE);
    scan5_k<<<5, 1024>>>(CUR, OFFS);
    cudaMemsetAsync(CUR, 0, 500000 * sizeof(int));
    fill5_k<<<dim3((NEDGE + 255) / 256, 5), 256>>>(ep, OFFS, CUR, SRCA, NEDGE);

    // --- merged layer-1 combine (relu fused, fp16 out into H1h) ---
    {
        CombBatch cb = make_comb(0);
        combine_batch<true><<<(200000 + 7) / 8, 256>>>(cb);
    }

    // --- merged layer-2 GEMM ---
    {
        GemmBatch gb = make_batch(1);
        gemm_batch<<<gb.ctaStart[3], 256, SMEM_V>>>(gb, K2S);
    }

    // --- merged layer-2 combine (relu fused, fp32 out) ---
    {
        CombBatch cb = make_comb(1);
        combine_batch<false><<<(200000 + 7) / 8, 256>>>(cb);
    }

    // --- head MLP ---
    gemm_tn<true><<<dim3(1, (N_ART + 127) / 128), 256>>>(
        out + 100000, hw1, hb1, Z, N_ART, 64, HIDD);
    head2_k<<<(N_ART + 255) / 256, 256>>>(Z, hw2, hb2, out, N_ART);
}